// round 7
// baseline (speedup 1.0000x reference)
#include <cuda_runtime.h>
#include <cstdint>
#include <cstddef>

#define S     8192
#define LC    16
#define CH    64
#define HW    256
#define TAGS  50

typedef unsigned long long ull;

// ---------------- device scratch ----------------
__device__ __align__(256) float g_char_feat[S * CH];        // 2 MB
__device__ __align__(256) float g_gpre[(size_t)S * 4 * HW]; // 32 MB
__device__ __align__(256) float g_wh[(size_t)S * HW];       // 8 MB

// ---------------- helpers ----------------
__device__ __forceinline__ ull ffma2(ull a, ull b, ull c) {
    ull d;
    asm("fma.rn.f32x2 %0, %1, %2, %3;" : "=l"(d) : "l"(a), "l"(b), "l"(c));
    return d;
}
__device__ __forceinline__ float f2sum(ull a) {
    float lo = __uint_as_float((unsigned)(a & 0xffffffffull));
    float hi = __uint_as_float((unsigned)(a >> 32));
    return lo + hi;
}
__device__ __forceinline__ float tanha(float x) {
    float y; asm("tanh.approx.f32 %0, %1;" : "=f"(y) : "f"(x)); return y;
}
__device__ __forceinline__ float sigm(float x) {       // 1 MUFU
    return fmaf(0.5f, tanha(0.5f * x), 0.5f);
}
__device__ __forceinline__ uint32_t smem_u32(const void* p) {
    return (uint32_t)__cvta_generic_to_shared(p);
}
__device__ __forceinline__ uint32_t cluster_rank() {
    uint32_t r; asm("mov.u32 %0, %%cluster_ctarank;" : "=r"(r)); return r;
}
__device__ __forceinline__ uint32_t mapa_sh(uint32_t addr, uint32_t rank) {
    uint32_t r;
    asm("mapa.shared::cluster.u32 %0, %1, %2;" : "=r"(r) : "r"(addr), "r"(rank));
    return r;
}
__device__ __forceinline__ void mbar_init(uint32_t addr, uint32_t cnt) {
    asm volatile("mbarrier.init.shared.b64 [%0], %1;" :: "r"(addr), "r"(cnt) : "memory");
}
__device__ __forceinline__ void mbar_expect_tx(uint32_t addr, uint32_t bytes) {
    asm volatile("mbarrier.arrive.expect_tx.shared.b64 _, [%0], %1;"
                 :: "r"(addr), "r"(bytes) : "memory");
}
__device__ __forceinline__ void st_async_b32(uint32_t dst, float v, uint32_t mbar) {
    asm volatile("st.async.shared::cluster.mbarrier::complete_tx::bytes.b32 [%0], %1, [%2];"
                 :: "r"(dst), "r"(__float_as_uint(v)), "r"(mbar) : "memory");
}
__device__ __forceinline__ void mbar_wait_parity(uint32_t mbar, uint32_t parity) {
    asm volatile(
        "{\n\t.reg .pred P;\n"
        "W%=:\n\t"
        "mbarrier.try_wait.parity.acquire.cluster.shared::cta.b64 P, [%0], %1, 0x989680;\n\t"
        "@!P bra W%=;\n\t"
        "}" :: "r"(mbar), "r"(parity) : "memory");
}
__device__ __forceinline__ void cluster_sync_() {
    asm volatile("barrier.cluster.arrive.aligned;\n\tbarrier.cluster.wait.aligned;" ::: "memory");
}

// =====================================================================
// Kernel 1: char LSTM
// =====================================================================
#define CA_SW   (512 * 68)
#define CA_EMB  (128 * 64)
#define CA_HB   (32 * 64)
#define CA_SB   256
#define CHAR_SMEM_BYTES ((CA_SW + CA_EMB + CA_HB + CA_SB) * 4 + 512 * 4)

__global__ void __launch_bounds__(512, 1)
char_lstm_kernel(const int* __restrict__ ci_g, const int* __restrict__ clen,
                 const float* __restrict__ cemb_g,
                 const float* __restrict__ Wih, const float* __restrict__ Whh,
                 const float* __restrict__ bih, const float* __restrict__ bhh)
{
    extern __shared__ float smA[];
    float* sW    = smA;
    float* cemb  = sW + CA_SW;
    float* hbuf  = cemb + CA_EMB;
    float* sb    = hbuf + CA_HB;
    int*   scidx = (int*)(sb + CA_SB);

    const int tid = threadIdx.x;
    const int wbase = blockIdx.x * 32;

    for (int idx = tid; idx < 512 * 16; idx += 512) {
        int row = idx >> 4, k4 = idx & 15;
        const float* src = (row < 256) ? Wih + (size_t)row * 64 + k4 * 4
                                       : Whh + (size_t)(row - 256) * 64 + k4 * 4;
        *(float4*)&sW[row * 68 + k4 * 4] = *(const float4*)src;
    }
    for (int idx = tid; idx < 128 * 16; idx += 512) {
        int row = idx >> 4, k4 = idx & 15;
        *(float4*)&cemb[row * 64 + k4 * 4] = *(const float4*)(cemb_g + (size_t)row * 64 + k4 * 4);
    }
    if (tid < 256) sb[tid] = bih[tid] + bhh[tid];
    scidx[tid] = ci_g[(size_t)wbase * 16 + tid];
    for (int idx = tid; idx < CA_HB; idx += 512) hbuf[idx] = 0.f;

    const int rt = tid & 63, wt = tid >> 6, w0 = wt * 4;
    int len[4]; float cc[4];
    #pragma unroll
    for (int i = 0; i < 4; i++) { len[i] = clen[wbase + w0 + i]; cc[i] = 0.f; }
    __syncthreads();

    for (int t = 0; t < LC; t++) {
        int ci[4];
        #pragma unroll
        for (int i = 0; i < 4; i++) ci[i] = scidx[(w0 + i) * 16 + t];

        ull acc[4][4];
        #pragma unroll
        for (int i = 0; i < 4; i++)
            #pragma unroll
            for (int q = 0; q < 4; q++) acc[i][q] = 0ull;

        #pragma unroll
        for (int k4 = 0; k4 < 16; k4++) {
            ulonglong2 wv[4];
            #pragma unroll
            for (int q = 0; q < 4; q++)
                wv[q] = *(const ulonglong2*)&sW[(q * 64 + rt) * 68 + k4 * 4];
            #pragma unroll
            for (int i = 0; i < 4; i++) {
                ulonglong2 xv = *(const ulonglong2*)&cemb[ci[i] * 64 + k4 * 4];
                #pragma unroll
                for (int q = 0; q < 4; q++) {
                    acc[i][q] = ffma2(xv.x, wv[q].x, acc[i][q]);
                    acc[i][q] = ffma2(xv.y, wv[q].y, acc[i][q]);
                }
            }
        }
        #pragma unroll
        for (int k4 = 0; k4 < 16; k4++) {
            ulonglong2 wv[4];
            #pragma unroll
            for (int q = 0; q < 4; q++)
                wv[q] = *(const ulonglong2*)&sW[(256 + q * 64 + rt) * 68 + k4 * 4];
            #pragma unroll
            for (int i = 0; i < 4; i++) {
                ulonglong2 hv = *(const ulonglong2*)&hbuf[(w0 + i) * 64 + k4 * 4];
                #pragma unroll
                for (int q = 0; q < 4; q++) {
                    acc[i][q] = ffma2(hv.x, wv[q].x, acc[i][q]);
                    acc[i][q] = ffma2(hv.y, wv[q].y, acc[i][q]);
                }
            }
        }
        __syncthreads();

        float bI = sb[rt], bF = sb[64 + rt], bG = sb[128 + rt], bO = sb[192 + rt];
        #pragma unroll
        for (int i = 0; i < 4; i++) {
            float gi = f2sum(acc[i][0]) + bI;
            float gf = f2sum(acc[i][1]) + bF;
            float gG = f2sum(acc[i][2]) + bG;
            float go = f2sum(acc[i][3]) + bO;
            cc[i] = fmaf(sigm(gf), cc[i], sigm(gi) * tanha(gG));
            float h = sigm(go) * tanha(cc[i]);
            hbuf[(w0 + i) * 64 + rt] = h;
            if (t == len[i] - 1)
                g_char_feat[(size_t)(wbase + w0 + i) * 64 + rt] = h;
        }
        __syncthreads();
    }
}

// =====================================================================
// Kernel 2: gpre
// =====================================================================
#define BP 196
#define GPRE_SMEM_BYTES ((16 + 64) * BP * 4)

__global__ void __launch_bounds__(256, 1)
gpre_kernel(const int* __restrict__ widx, const float* __restrict__ wemb,
            const float* __restrict__ Wih,
            const float* __restrict__ bih, const float* __restrict__ bhh)
{
    extern __shared__ float smB[];
    float* sx = smB;
    float* sw = smB + 16 * BP;

    const int tid = threadIdx.x;
    const int t0 = blockIdx.x * 16;
    const int G0 = blockIdx.y * 64;

    for (int i = tid; i < 16 * 48; i += 256) {
        int tt = i / 48, k4 = i % 48;
        float4 v = (k4 < 32)
            ? *(const float4*)(wemb + (size_t)widx[t0 + tt] * 128 + k4 * 4)
            : *(const float4*)(g_char_feat + (size_t)(t0 + tt) * 64 + (k4 - 32) * 4);
        *(float4*)&sx[tt * BP + k4 * 4] = v;
    }
    for (int i = tid; i < 64 * 48; i += 256) {
        int r = i / 48, k4 = i % 48;
        *(float4*)&sw[r * BP + k4 * 4] = *(const float4*)(Wih + (size_t)(G0 + r) * 192 + k4 * 4);
    }
    __syncthreads();

    const int g = tid & 63, tq = tid >> 6;
    ull ax[4], ay[4];
    #pragma unroll
    for (int i = 0; i < 4; i++) { ax[i] = 0ull; ay[i] = 0ull; }

    #pragma unroll 4
    for (int k4 = 0; k4 < 48; k4++) {
        ulonglong2 wv = *(const ulonglong2*)&sw[g * BP + k4 * 4];
        #pragma unroll
        for (int it = 0; it < 4; it++) {
            ulonglong2 xv = *(const ulonglong2*)&sx[(tq * 4 + it) * BP + k4 * 4];
            ax[it] = ffma2(xv.x, wv.x, ax[it]);
            ay[it] = ffma2(xv.y, wv.y, ay[it]);
        }
    }
    float b = bih[G0 + g] + bhh[G0 + g];
    #pragma unroll
    for (int it = 0; it < 4; it++)
        g_gpre[(size_t)(t0 + tq * 4 + it) * 1024 + G0 + g] = f2sum(ax[it]) + f2sum(ay[it]) + b;
}

// =====================================================================
// Kernel 3: word LSTM. 8-CTA cluster, st.async tx barriers (round-5
// structure). New lane map: lane = u2*8 + q*2 + half:
//   u2 (0..3) unit-within-warp, q (0..3) gate, half (0..1) k-half.
// Each thread: 1 gate row x 128 k = 64 ffma2 (same fma floor), but the
// reduction is 1 shfl_xor + 3 independent shfl_down (vs 3 dependent
// rounds x 4 gates). Writers = lanes 0/8/16/24 of every warp, same
// st.async packing as round 5.
// =====================================================================
__global__ void __launch_bounds__(256, 1) __cluster_dims__(8, 1, 1)
word_lstm_kernel(const float* __restrict__ Whh)
{
    __shared__ float sh[2][256];
    __shared__ __align__(8) unsigned long long bar2[2];

    const int tid  = threadIdx.x;
    const int lane = tid & 31, w = tid >> 5;
    const int u2   = lane >> 3;         // unit within warp-group
    const int q    = (lane >> 1) & 3;   // gate
    const int half = lane & 1;          // k half
    const uint32_t rank = cluster_rank();
    const int ul    = w * 4 + u2;       // 0..31 local unit
    const int uglob = (int)rank * 32 + ul;
    const int grow  = q * 256 + uglob;  // global gate row

    // weights: this thread's gate row, k in [half*128, half*128+128)
    ulonglong2 rw[32];
    {
        const ulonglong2* wp = (const ulonglong2*)(Whh + (size_t)grow * 256 + half * 128);
        #pragma unroll
        for (int i = 0; i < 32; i++) rw[i] = wp[i];
    }

    sh[0][tid] = 0.f;
    sh[1][tid] = 0.f;
    const uint32_t locb0 = smem_u32(&bar2[0]);
    const uint32_t locb1 = smem_u32(&bar2[1]);
    if (tid == 0) {
        mbar_init(locb0, 1);
        mbar_init(locb1, 1);
        mbar_expect_tx(locb0, 1024);
        mbar_expect_tx(locb1, 1024);
    }
    __syncthreads();
    cluster_sync_();

    // per-writer store tables: unit uglob's slot in every dest CTA
    uint32_t dstE[8], dstO[8], brE[8], brO[8];
    {
        uint32_t aE = smem_u32(&sh[1][uglob]);
        uint32_t aO = smem_u32(&sh[0][uglob]);
        #pragma unroll
        for (int dr = 0; dr < 8; dr++) {
            dstE[dr] = mapa_sh(aE, dr);
            dstO[dr] = mapa_sh(aO, dr);
            brE[dr]  = mapa_sh(locb1, dr);
            brO[dr]  = mapa_sh(locb0, dr);
        }
    }

    float c = 0.f;
    uint32_t p0 = 0, p1 = 0;
    const bool is_writer = ((lane & 7) == 0);   // q==0, half==0

    for (int t = 0; t < S; t++) {
        // prefetch gate-preactivations (writer lanes; overlaps wait)
        float gp0 = 0.f, gp1 = 0.f, gp2 = 0.f, gp3 = 0.f;
        if (is_writer) {
            const float* gpp = g_gpre + (size_t)t * 1024 + uglob;
            gp0 = gpp[0]; gp1 = gpp[256]; gp2 = gpp[512]; gp3 = gpp[768];
        }

        const int b = t & 1;
        if (t > 0) {
            if (b == 0) {
                mbar_wait_parity(locb0, p0); p0 ^= 1;
                if (tid == 0) mbar_expect_tx(locb0, 1024);
            } else {
                mbar_wait_parity(locb1, p1); p1 ^= 1;
                if (tid == 0) mbar_expect_tx(locb1, 1024);
            }
        }

        // matvec: 32 LDS.128 (2-addr broadcast) + 64 ffma2, 4 acc chains
        const ulonglong2* hb = (const ulonglong2*)&sh[b][half * 128];
        ull a0 = 0, a1 = 0, a2 = 0, a3 = 0;
        #pragma unroll
        for (int i = 0; i < 32; i += 2) {
            ulonglong2 h0 = hb[i], h1 = hb[i + 1];
            a0 = ffma2(h0.x, rw[i].x, a0);
            a1 = ffma2(h0.y, rw[i].y, a1);
            a2 = ffma2(h1.x, rw[i + 1].x, a2);
            a3 = ffma2(h1.y, rw[i + 1].y, a3);
        }
        float s = (f2sum(a0) + f2sum(a1)) + (f2sum(a2) + f2sum(a3));
        // combine k halves (lanes l, l^1)
        s += __shfl_xor_sync(0xFFFFFFFFu, s, 1);
        // gather gates q=1..3 (lanes +2, +4, +6) — independent shuffles
        float g1 = __shfl_down_sync(0xFFFFFFFFu, s, 2);
        float g2 = __shfl_down_sync(0xFFFFFFFFu, s, 4);
        float g3 = __shfl_down_sync(0xFFFFFFFFu, s, 6);

        float s0 = s + gp0, s1 = g1 + gp1, s2 = g2 + gp2, s3 = g3 + gp3;
        c = fmaf(sigm(s1), c, sigm(s0) * tanha(s2));
        float h = sigm(s3) * tanha(c);

        if (is_writer) {
            if (t < S - 1) {
                if (b == 0) {
                    #pragma unroll
                    for (int dr = 0; dr < 8; dr++) st_async_b32(dstE[dr], h, brE[dr]);
                } else {
                    #pragma unroll
                    for (int dr = 0; dr < 8; dr++) st_async_b32(dstO[dr], h, brO[dr]);
                }
            }
            g_wh[(size_t)t * HW + uglob] = h;
        }
    }
}

// =====================================================================
// Kernel 4: tag head + log_softmax. 256 blocks x 32 tokens, tagW staged
// per block (transposed [k][64]), warp-per-token, shfl softmax.
// =====================================================================
#define TAG_SW   (256 * 64)
#define TAG_SMEM_BYTES ((TAG_SW + 64) * 4)

__global__ void __launch_bounds__(256, 1)
tag_kernel(const float* __restrict__ tagW, const float* __restrict__ tagb,
           float* __restrict__ out)
{
    extern __shared__ float smT[];
    float* sw = smT;
    float* sb = smT + TAG_SW;

    const int tid = threadIdx.x;
    const int lane = tid & 31, warp = tid >> 5;

    for (int i = tid; i < TAG_SW; i += 256) sw[i] = 0.f;
    if (tid < 64) sb[tid] = (tid < TAGS) ? tagb[tid] : 0.f;
    __syncthreads();
    for (int i = tid; i < TAGS * 256; i += 256) {
        int tg = i >> 8, k = i & 255;
        sw[k * 64 + tg] = tagW[i];
    }
    __syncthreads();

    const bool v1 = (32 + lane) < TAGS;

    #pragma unroll 1
    for (int it = 0; it < 4; it++) {
        const int token = blockIdx.x * 32 + it * 8 + warp;
        const float4* hp4 = (const float4*)(g_wh + (size_t)token * 256);

        float a0 = 0.f, a1 = 0.f;
        #pragma unroll 8
        for (int k4 = 0; k4 < 64; k4++) {
            float4 h = hp4[k4];
            const float* p = sw + k4 * 256 + lane;
            a0 = fmaf(h.x, p[0],   a0);  a1 = fmaf(h.x, p[32],  a1);
            a0 = fmaf(h.y, p[64],  a0);  a1 = fmaf(h.y, p[96],  a1);
            a0 = fmaf(h.z, p[128], a0);  a1 = fmaf(h.z, p[160], a1);
            a0 = fmaf(h.w, p[192], a0);  a1 = fmaf(h.w, p[224], a1);
        }
        a0 += sb[lane];
        a1 += sb[32 + lane];

        float m = fmaxf(a0, v1 ? a1 : -3.4e38f);
        #pragma unroll
        for (int off = 16; off; off >>= 1)
            m = fmaxf(m, __shfl_xor_sync(0xFFFFFFFFu, m, off));
        float e = __expf(a0 - m) + (v1 ? __expf(a1 - m) : 0.f);
        #pragma unroll
        for (int off = 16; off; off >>= 1)
            e += __shfl_xor_sync(0xFFFFFFFFu, e, off);
        float ls = __logf(e);

        out[(size_t)token * TAGS + lane] = a0 - m - ls;
        if (v1) out[(size_t)token * TAGS + 32 + lane] = a1 - m - ls;
    }
}

// =====================================================================
extern "C" void kernel_launch(void* const* d_in, const int* in_sizes, int n_in,
                              void* d_out, int out_size)
{
    const int*   word_idxs = (const int*)d_in[0];
    const int*   char_idxs = (const int*)d_in[1];
    const int*   char_lens = (const int*)d_in[2];
    const float* char_emb  = (const float*)d_in[3];
    const float* char_Wih  = (const float*)d_in[4];
    const float* char_Whh  = (const float*)d_in[5];
    const float* char_bih  = (const float*)d_in[6];
    const float* char_bhh  = (const float*)d_in[7];
    const float* word_emb  = (const float*)d_in[8];
    const float* word_Wih  = (const float*)d_in[9];
    const float* word_Whh  = (const float*)d_in[10];
    const float* word_bih  = (const float*)d_in[11];
    const float* word_bhh  = (const float*)d_in[12];
    const float* tag_W     = (const float*)d_in[13];
    const float* tag_b     = (const float*)d_in[14];
    float* out = (float*)d_out;

    cudaFuncSetAttribute(char_lstm_kernel,
                         cudaFuncAttributeMaxDynamicSharedMemorySize, CHAR_SMEM_BYTES);
    cudaFuncSetAttribute(gpre_kernel,
                         cudaFuncAttributeMaxDynamicSharedMemorySize, GPRE_SMEM_BYTES);
    cudaFuncSetAttribute(tag_kernel,
                         cudaFuncAttributeMaxDynamicSharedMemorySize, TAG_SMEM_BYTES);

    char_lstm_kernel<<<256, 512, CHAR_SMEM_BYTES>>>(
        char_idxs, char_lens, char_emb, char_Wih, char_Whh, char_bih, char_bhh);

    dim3 gb(S / 16, 1024 / 64);
    gpre_kernel<<<gb, 256, GPRE_SMEM_BYTES>>>(
        word_idxs, word_emb, word_Wih, word_bih, word_bhh);

    word_lstm_kernel<<<8, 256>>>(word_Whh);

    tag_kernel<<<S / 32, 256, TAG_SMEM_BYTES>>>(tag_W, tag_b, out);
}

// round 8
// speedup vs baseline: 1.5996x; 1.5996x over previous
#include <cuda_runtime.h>
#include <cstdint>
#include <cstddef>

#define S     8192
#define LC    16
#define CH    64
#define HW    256
#define TAGS  50

typedef unsigned long long ull;

// ---------------- device scratch ----------------
__device__ __align__(256) float g_char_feat[S * CH];        // 2 MB
__device__ __align__(256) float g_gpre[(size_t)S * 4 * HW]; // 32 MB
__device__ __align__(256) float g_wh[(size_t)S * HW];       // 8 MB

// ---------------- helpers ----------------
__device__ __forceinline__ ull ffma2(ull a, ull b, ull c) {
    ull d;
    asm("fma.rn.f32x2 %0, %1, %2, %3;" : "=l"(d) : "l"(a), "l"(b), "l"(c));
    return d;
}
__device__ __forceinline__ float f2sum(ull a) {
    float lo = __uint_as_float((unsigned)(a & 0xffffffffull));
    float hi = __uint_as_float((unsigned)(a >> 32));
    return lo + hi;
}
__device__ __forceinline__ float tanha(float x) {
    float y; asm("tanh.approx.f32 %0, %1;" : "=f"(y) : "f"(x)); return y;
}
__device__ __forceinline__ float sigm(float x) {       // 1 MUFU
    return fmaf(0.5f, tanha(0.5f * x), 0.5f);
}
__device__ __forceinline__ uint32_t smem_u32(const void* p) {
    return (uint32_t)__cvta_generic_to_shared(p);
}
__device__ __forceinline__ uint32_t cluster_rank() {
    uint32_t r; asm("mov.u32 %0, %%cluster_ctarank;" : "=r"(r)); return r;
}
__device__ __forceinline__ uint32_t mapa_sh(uint32_t addr, uint32_t rank) {
    uint32_t r;
    asm("mapa.shared::cluster.u32 %0, %1, %2;" : "=r"(r) : "r"(addr), "r"(rank));
    return r;
}
__device__ __forceinline__ void mbar_init(uint32_t addr, uint32_t cnt) {
    asm volatile("mbarrier.init.shared.b64 [%0], %1;" :: "r"(addr), "r"(cnt) : "memory");
}
__device__ __forceinline__ void mbar_expect_tx(uint32_t addr, uint32_t bytes) {
    asm volatile("mbarrier.arrive.expect_tx.shared.b64 _, [%0], %1;"
                 :: "r"(addr), "r"(bytes) : "memory");
}
__device__ __forceinline__ void st_async_b32(uint32_t dst, float v, uint32_t mbar) {
    asm volatile("st.async.shared::cluster.mbarrier::complete_tx::bytes.b32 [%0], %1, [%2];"
                 :: "r"(dst), "r"(__float_as_uint(v)), "r"(mbar) : "memory");
}
__device__ __forceinline__ void mbar_wait_parity(uint32_t mbar, uint32_t parity) {
    asm volatile(
        "{\n\t.reg .pred P;\n"
        "W%=:\n\t"
        "mbarrier.try_wait.parity.acquire.cluster.shared::cta.b64 P, [%0], %1, 0x989680;\n\t"
        "@!P bra W%=;\n\t"
        "}" :: "r"(mbar), "r"(parity) : "memory");
}
__device__ __forceinline__ void cluster_sync_() {
    asm volatile("barrier.cluster.arrive.aligned;\n\tbarrier.cluster.wait.aligned;" ::: "memory");
}

// =====================================================================
// Kernel 1: char LSTM
// =====================================================================
#define CA_SW   (512 * 68)
#define CA_EMB  (128 * 64)
#define CA_HB   (32 * 64)
#define CA_SB   256
#define CHAR_SMEM_BYTES ((CA_SW + CA_EMB + CA_HB + CA_SB) * 4 + 512 * 4)

__global__ void __launch_bounds__(512, 1)
char_lstm_kernel(const int* __restrict__ ci_g, const int* __restrict__ clen,
                 const float* __restrict__ cemb_g,
                 const float* __restrict__ Wih, const float* __restrict__ Whh,
                 const float* __restrict__ bih, const float* __restrict__ bhh)
{
    extern __shared__ float smA[];
    float* sW    = smA;
    float* cemb  = sW + CA_SW;
    float* hbuf  = cemb + CA_EMB;
    float* sb    = hbuf + CA_HB;
    int*   scidx = (int*)(sb + CA_SB);

    const int tid = threadIdx.x;
    const int wbase = blockIdx.x * 32;

    for (int idx = tid; idx < 512 * 16; idx += 512) {
        int row = idx >> 4, k4 = idx & 15;
        const float* src = (row < 256) ? Wih + (size_t)row * 64 + k4 * 4
                                       : Whh + (size_t)(row - 256) * 64 + k4 * 4;
        *(float4*)&sW[row * 68 + k4 * 4] = *(const float4*)src;
    }
    for (int idx = tid; idx < 128 * 16; idx += 512) {
        int row = idx >> 4, k4 = idx & 15;
        *(float4*)&cemb[row * 64 + k4 * 4] = *(const float4*)(cemb_g + (size_t)row * 64 + k4 * 4);
    }
    if (tid < 256) sb[tid] = bih[tid] + bhh[tid];
    scidx[tid] = ci_g[(size_t)wbase * 16 + tid];
    for (int idx = tid; idx < CA_HB; idx += 512) hbuf[idx] = 0.f;

    const int rt = tid & 63, wt = tid >> 6, w0 = wt * 4;
    int len[4]; float cc[4];
    #pragma unroll
    for (int i = 0; i < 4; i++) { len[i] = clen[wbase + w0 + i]; cc[i] = 0.f; }
    __syncthreads();

    for (int t = 0; t < LC; t++) {
        int ci[4];
        #pragma unroll
        for (int i = 0; i < 4; i++) ci[i] = scidx[(w0 + i) * 16 + t];

        ull acc[4][4];
        #pragma unroll
        for (int i = 0; i < 4; i++)
            #pragma unroll
            for (int q = 0; q < 4; q++) acc[i][q] = 0ull;

        #pragma unroll
        for (int k4 = 0; k4 < 16; k4++) {
            ulonglong2 wv[4];
            #pragma unroll
            for (int q = 0; q < 4; q++)
                wv[q] = *(const ulonglong2*)&sW[(q * 64 + rt) * 68 + k4 * 4];
            #pragma unroll
            for (int i = 0; i < 4; i++) {
                ulonglong2 xv = *(const ulonglong2*)&cemb[ci[i] * 64 + k4 * 4];
                #pragma unroll
                for (int q = 0; q < 4; q++) {
                    acc[i][q] = ffma2(xv.x, wv[q].x, acc[i][q]);
                    acc[i][q] = ffma2(xv.y, wv[q].y, acc[i][q]);
                }
            }
        }
        #pragma unroll
        for (int k4 = 0; k4 < 16; k4++) {
            ulonglong2 wv[4];
            #pragma unroll
            for (int q = 0; q < 4; q++)
                wv[q] = *(const ulonglong2*)&sW[(256 + q * 64 + rt) * 68 + k4 * 4];
            #pragma unroll
            for (int i = 0; i < 4; i++) {
                ulonglong2 hv = *(const ulonglong2*)&hbuf[(w0 + i) * 64 + k4 * 4];
                #pragma unroll
                for (int q = 0; q < 4; q++) {
                    acc[i][q] = ffma2(hv.x, wv[q].x, acc[i][q]);
                    acc[i][q] = ffma2(hv.y, wv[q].y, acc[i][q]);
                }
            }
        }
        __syncthreads();

        float bI = sb[rt], bF = sb[64 + rt], bG = sb[128 + rt], bO = sb[192 + rt];
        #pragma unroll
        for (int i = 0; i < 4; i++) {
            float gi = f2sum(acc[i][0]) + bI;
            float gf = f2sum(acc[i][1]) + bF;
            float gG = f2sum(acc[i][2]) + bG;
            float go = f2sum(acc[i][3]) + bO;
            cc[i] = fmaf(sigm(gf), cc[i], sigm(gi) * tanha(gG));
            float h = sigm(go) * tanha(cc[i]);
            hbuf[(w0 + i) * 64 + rt] = h;
            if (t == len[i] - 1)
                g_char_feat[(size_t)(wbase + w0 + i) * 64 + rt] = h;
        }
        __syncthreads();
    }
}

// =====================================================================
// Kernel 2: gpre
// =====================================================================
#define BP 196
#define GPRE_SMEM_BYTES ((16 + 64) * BP * 4)

__global__ void __launch_bounds__(256, 1)
gpre_kernel(const int* __restrict__ widx, const float* __restrict__ wemb,
            const float* __restrict__ Wih,
            const float* __restrict__ bih, const float* __restrict__ bhh)
{
    extern __shared__ float smB[];
    float* sx = smB;
    float* sw = smB + 16 * BP;

    const int tid = threadIdx.x;
    const int t0 = blockIdx.x * 16;
    const int G0 = blockIdx.y * 64;

    for (int i = tid; i < 16 * 48; i += 256) {
        int tt = i / 48, k4 = i % 48;
        float4 v = (k4 < 32)
            ? *(const float4*)(wemb + (size_t)widx[t0 + tt] * 128 + k4 * 4)
            : *(const float4*)(g_char_feat + (size_t)(t0 + tt) * 64 + (k4 - 32) * 4);
        *(float4*)&sx[tt * BP + k4 * 4] = v;
    }
    for (int i = tid; i < 64 * 48; i += 256) {
        int r = i / 48, k4 = i % 48;
        *(float4*)&sw[r * BP + k4 * 4] = *(const float4*)(Wih + (size_t)(G0 + r) * 192 + k4 * 4);
    }
    __syncthreads();

    const int g = tid & 63, tq = tid >> 6;
    ull ax[4], ay[4];
    #pragma unroll
    for (int i = 0; i < 4; i++) { ax[i] = 0ull; ay[i] = 0ull; }

    #pragma unroll 4
    for (int k4 = 0; k4 < 48; k4++) {
        ulonglong2 wv = *(const ulonglong2*)&sw[g * BP + k4 * 4];
        #pragma unroll
        for (int it = 0; it < 4; it++) {
            ulonglong2 xv = *(const ulonglong2*)&sx[(tq * 4 + it) * BP + k4 * 4];
            ax[it] = ffma2(xv.x, wv.x, ax[it]);
            ay[it] = ffma2(xv.y, wv.y, ay[it]);
        }
    }
    float b = bih[G0 + g] + bhh[G0 + g];
    #pragma unroll
    for (int it = 0; it < 4; it++)
        g_gpre[(size_t)(t0 + tq * 4 + it) * 1024 + G0 + g] = f2sum(ax[it]) + f2sum(ay[it]) + b;
}

// =====================================================================
// Kernel 3: word LSTM. 8-CTA cluster, st.async tx barriers.
// ROUND-5 DATA PATH (proven fastest), branch-free interior loop:
//   - wait barrier/address selected arithmetically (locb0 + (b<<3)),
//     parity = ((t-1)>>1)&1
//   - store targets derived by offset: odd step = even-step addr -1024/-8
//   - t=0 (no wait) and t=S-1 (no fabric store) peeled out of the loop
// =====================================================================
__global__ void __launch_bounds__(256, 1) __cluster_dims__(8, 1, 1)
word_lstm_kernel(const float* __restrict__ Whh)
{
    __shared__ float sh[2][256];                      // sh[1] = sh[0] + 1024 B
    __shared__ __align__(8) unsigned long long bar2[2]; // bar2[1] = bar2[0] + 8 B

    const int tid = threadIdx.x;
    const int jj  = tid >> 3;     // 0..31 h-unit
    const int oct = tid & 7;      // k octant
    const uint32_t rank = cluster_rank();
    const int uglob = (int)rank * 32 + jj;

    // weights: rw[q][m] covers gate row (q*256 + uglob), k = oct*4 + m*32
    ulonglong2 rw0[8], rw1[8], rw2[8], rw3[8];
    {
        const float* base = Whh + (size_t)uglob * 256 + oct * 4;
        #pragma unroll
        for (int m = 0; m < 8; m++) {
            rw0[m] = *(const ulonglong2*)(base + 0 * 65536 + m * 32);
            rw1[m] = *(const ulonglong2*)(base + 1 * 65536 + m * 32);
            rw2[m] = *(const ulonglong2*)(base + 2 * 65536 + m * 32);
            rw3[m] = *(const ulonglong2*)(base + 3 * 65536 + m * 32);
        }
    }

    sh[0][tid] = 0.f;
    sh[1][tid] = 0.f;
    const uint32_t locb0 = smem_u32(&bar2[0]);
    const uint32_t locb1 = smem_u32(&bar2[1]);
    if (tid == 0) {
        mbar_init(locb0, 1);
        mbar_init(locb1, 1);
        mbar_expect_tx(locb0, 1024);
        mbar_expect_tx(locb1, 1024);
    }
    __syncthreads();
    cluster_sync_();

    // even-step tables (write sh[1]/bar1); odd step derives by -1024 / -8
    uint32_t dstE[8], brE[8];
    {
        uint32_t aE = smem_u32(&sh[1][uglob]);
        #pragma unroll
        for (int dr = 0; dr < 8; dr++) {
            dstE[dr] = mapa_sh(aE, dr);
            brE[dr]  = mapa_sh(locb1, dr);
        }
    }

    float c = 0.f;
    const bool is_writer = (oct == 0);

    // ---------- t = 0 (no wait; h = f(gpre) with h_prev = 0, c_prev = 0) ----------
    if (is_writer) {
        const float* gpp = g_gpre;
        float gp0 = gpp[uglob], gp1 = gpp[256 + uglob];
        float gp2 = gpp[512 + uglob], gp3 = gpp[768 + uglob];
        c = sigm(gp0) * tanha(gp2);
        float h = sigm(gp3) * tanha(c);
        #pragma unroll
        for (int dr = 0; dr < 8; dr++) st_async_b32(dstE[dr], h, brE[dr]);
        g_wh[uglob] = h;
    }

    // ---------- interior t = 1 .. S-2 (branch-free) ----------
    for (int t = 1; t < S - 1; t++) {
        const uint32_t b = (uint32_t)t & 1u;

        float gp0 = 0.f, gp1 = 0.f, gp2 = 0.f, gp3 = 0.f;
        if (is_writer) {
            const float* gpp = g_gpre + (size_t)t * 1024 + uglob;
            gp0 = gpp[0]; gp1 = gpp[256]; gp2 = gpp[512]; gp3 = gpp[768];
        }

        const uint32_t wbar = locb0 + (b << 3);
        mbar_wait_parity(wbar, ((uint32_t)(t - 1) >> 1) & 1u);
        if (tid == 0) mbar_expect_tx(wbar, 1024);

        // matvec: 8 conflict-free LDS.128 + 64 ffma2
        const ulonglong2* hb = (const ulonglong2*)((const char*)sh + (b << 10));
        ull a0 = 0, a1 = 0, a2 = 0, a3 = 0;
        #pragma unroll
        for (int m = 0; m < 8; m++) {
            ulonglong2 hv = hb[oct + m * 8];
            a0 = ffma2(hv.x, rw0[m].x, a0); a0 = ffma2(hv.y, rw0[m].y, a0);
            a1 = ffma2(hv.x, rw1[m].x, a1); a1 = ffma2(hv.y, rw1[m].y, a1);
            a2 = ffma2(hv.x, rw2[m].x, a2); a2 = ffma2(hv.y, rw2[m].y, a2);
            a3 = ffma2(hv.x, rw3[m].x, a3); a3 = ffma2(hv.y, rw3[m].y, a3);
        }
        float s0 = f2sum(a0), s1 = f2sum(a1), s2 = f2sum(a2), s3 = f2sum(a3);
        #pragma unroll
        for (int off = 1; off <= 4; off <<= 1) {
            s0 += __shfl_xor_sync(0xFFFFFFFFu, s0, off);
            s1 += __shfl_xor_sync(0xFFFFFFFFu, s1, off);
            s2 += __shfl_xor_sync(0xFFFFFFFFu, s2, off);
            s3 += __shfl_xor_sync(0xFFFFFFFFu, s3, off);
        }

        s0 += gp0; s1 += gp1; s2 += gp2; s3 += gp3;
        c = fmaf(sigm(s1), c, sigm(s0) * tanha(s2));
        float h = sigm(s3) * tanha(c);

        if (is_writer) {
            const uint32_t doff = b << 10;   // odd step writes sh[0] = sh[1]-1024
            const uint32_t boff = b << 3;    // odd step arrives bar[0] = bar[1]-8
            #pragma unroll
            for (int dr = 0; dr < 8; dr++)
                st_async_b32(dstE[dr] - doff, h, brE[dr] - boff);
            g_wh[(size_t)t * HW + uglob] = h;
        }
    }

    // ---------- t = S-1 (wait + compute, no fabric store) ----------
    {
        const int t = S - 1;
        const uint32_t b = (uint32_t)t & 1u;

        float gp0 = 0.f, gp1 = 0.f, gp2 = 0.f, gp3 = 0.f;
        if (is_writer) {
            const float* gpp = g_gpre + (size_t)t * 1024 + uglob;
            gp0 = gpp[0]; gp1 = gpp[256]; gp2 = gpp[512]; gp3 = gpp[768];
        }

        const uint32_t wbar = locb0 + (b << 3);
        mbar_wait_parity(wbar, ((uint32_t)(t - 1) >> 1) & 1u);

        const ulonglong2* hb = (const ulonglong2*)((const char*)sh + (b << 10));
        ull a0 = 0, a1 = 0, a2 = 0, a3 = 0;
        #pragma unroll
        for (int m = 0; m < 8; m++) {
            ulonglong2 hv = hb[oct + m * 8];
            a0 = ffma2(hv.x, rw0[m].x, a0); a0 = ffma2(hv.y, rw0[m].y, a0);
            a1 = ffma2(hv.x, rw1[m].x, a1); a1 = ffma2(hv.y, rw1[m].y, a1);
            a2 = ffma2(hv.x, rw2[m].x, a2); a2 = ffma2(hv.y, rw2[m].y, a2);
            a3 = ffma2(hv.x, rw3[m].x, a3); a3 = ffma2(hv.y, rw3[m].y, a3);
        }
        float s0 = f2sum(a0), s1 = f2sum(a1), s2 = f2sum(a2), s3 = f2sum(a3);
        #pragma unroll
        for (int off = 1; off <= 4; off <<= 1) {
            s0 += __shfl_xor_sync(0xFFFFFFFFu, s0, off);
            s1 += __shfl_xor_sync(0xFFFFFFFFu, s1, off);
            s2 += __shfl_xor_sync(0xFFFFFFFFu, s2, off);
            s3 += __shfl_xor_sync(0xFFFFFFFFu, s3, off);
        }

        s0 += gp0; s1 += gp1; s2 += gp2; s3 += gp3;
        c = fmaf(sigm(s1), c, sigm(s0) * tanha(s2));
        float h = sigm(s3) * tanha(c);

        if (is_writer)
            g_wh[(size_t)t * HW + uglob] = h;
    }
}

// =====================================================================
// Kernel 4: tag head + log_softmax. 256 blocks x 32 tokens.
// =====================================================================
#define TAG_SW   (256 * 64)
#define TAG_SMEM_BYTES ((TAG_SW + 64) * 4)

__global__ void __launch_bounds__(256, 1)
tag_kernel(const float* __restrict__ tagW, const float* __restrict__ tagb,
           float* __restrict__ out)
{
    extern __shared__ float smT[];
    float* sw = smT;
    float* sb = smT + TAG_SW;

    const int tid = threadIdx.x;
    const int lane = tid & 31, warp = tid >> 5;

    for (int i = tid; i < TAG_SW; i += 256) sw[i] = 0.f;
    if (tid < 64) sb[tid] = (tid < TAGS) ? tagb[tid] : 0.f;
    __syncthreads();
    for (int i = tid; i < TAGS * 256; i += 256) {
        int tg = i >> 8, k = i & 255;
        sw[k * 64 + tg] = tagW[i];
    }
    __syncthreads();

    const bool v1 = (32 + lane) < TAGS;

    #pragma unroll 1
    for (int it = 0; it < 4; it++) {
        const int token = blockIdx.x * 32 + it * 8 + warp;
        const float4* hp4 = (const float4*)(g_wh + (size_t)token * 256);

        float a0 = 0.f, a1 = 0.f;
        #pragma unroll 8
        for (int k4 = 0; k4 < 64; k4++) {
            float4 h = hp4[k4];
            const float* p = sw + k4 * 256 + lane;
            a0 = fmaf(h.x, p[0],   a0);  a1 = fmaf(h.x, p[32],  a1);
            a0 = fmaf(h.y, p[64],  a0);  a1 = fmaf(h.y, p[96],  a1);
            a0 = fmaf(h.z, p[128], a0);  a1 = fmaf(h.z, p[160], a1);
            a0 = fmaf(h.w, p[192], a0);  a1 = fmaf(h.w, p[224], a1);
        }
        a0 += sb[lane];
        a1 += sb[32 + lane];

        float m = fmaxf(a0, v1 ? a1 : -3.4e38f);
        #pragma unroll
        for (int off = 16; off; off >>= 1)
            m = fmaxf(m, __shfl_xor_sync(0xFFFFFFFFu, m, off));
        float e = __expf(a0 - m) + (v1 ? __expf(a1 - m) : 0.f);
        #pragma unroll
        for (int off = 16; off; off >>= 1)
            e += __shfl_xor_sync(0xFFFFFFFFu, e, off);
        float ls = __logf(e);

        out[(size_t)token * TAGS + lane] = a0 - m - ls;
        if (v1) out[(size_t)token * TAGS + 32 + lane] = a1 - m - ls;
    }
}

// =====================================================================
extern "C" void kernel_launch(void* const* d_in, const int* in_sizes, int n_in,
                              void* d_out, int out_size)
{
    const int*   word_idxs = (const int*)d_in[0];
    const int*   char_idxs = (const int*)d_in[1];
    const int*   char_lens = (const int*)d_in[2];
    const float* char_emb  = (const float*)d_in[3];
    const float* char_Wih  = (const float*)d_in[4];
    const float* char_Whh  = (const float*)d_in[5];
    const float* char_bih  = (const float*)d_in[6];
    const float* char_bhh  = (const float*)d_in[7];
    const float* word_emb  = (const float*)d_in[8];
    const float* word_Wih  = (const float*)d_in[9];
    const float* word_Whh  = (const float*)d_in[10];
    const float* word_bih  = (const float*)d_in[11];
    const float* word_bhh  = (const float*)d_in[12];
    const float* tag_W     = (const float*)d_in[13];
    const float* tag_b     = (const float*)d_in[14];
    float* out = (float*)d_out;

    cudaFuncSetAttribute(char_lstm_kernel,
                         cudaFuncAttributeMaxDynamicSharedMemorySize, CHAR_SMEM_BYTES);
    cudaFuncSetAttribute(gpre_kernel,
                         cudaFuncAttributeMaxDynamicSharedMemorySize, GPRE_SMEM_BYTES);
    cudaFuncSetAttribute(tag_kernel,
                         cudaFuncAttributeMaxDynamicSharedMemorySize, TAG_SMEM_BYTES);

    char_lstm_kernel<<<256, 512, CHAR_SMEM_BYTES>>>(
        char_idxs, char_lens, char_emb, char_Wih, char_Whh, char_bih, char_bhh);

    dim3 gb(S / 16, 1024 / 64);
    gpre_kernel<<<gb, 256, GPRE_SMEM_BYTES>>>(
        word_idxs, word_emb, word_Wih, word_bih, word_bhh);

    word_lstm_kernel<<<8, 256>>>(word_Whh);

    tag_kernel<<<S / 32, 256, TAG_SMEM_BYTES>>>(tag_W, tag_b, out);
}

// round 10
// speedup vs baseline: 1.6251x; 1.0159x over previous
#include <cuda_runtime.h>
#include <cstdint>
#include <cstddef>

#define S     8192
#define LC    16
#define CH    64
#define HW    256
#define TAGS  50

typedef unsigned long long ull;

// ---------------- device scratch ----------------
__device__ __align__(256) float g_char_feat[S * CH];        // 2 MB
__device__ __align__(256) float g_gpre[(size_t)S * 4 * HW]; // 32 MB
__device__ __align__(256) float g_wh[(size_t)S * HW];       // 8 MB

// ---------------- helpers ----------------
__device__ __forceinline__ ull ffma2(ull a, ull b, ull c) {
    ull d;
    asm("fma.rn.f32x2 %0, %1, %2, %3;" : "=l"(d) : "l"(a), "l"(b), "l"(c));
    return d;
}
__device__ __forceinline__ float f2sum(ull a) {
    float lo = __uint_as_float((unsigned)(a & 0xffffffffull));
    float hi = __uint_as_float((unsigned)(a >> 32));
    return lo + hi;
}
__device__ __forceinline__ float tanha(float x) {
    float y; asm("tanh.approx.f32 %0, %1;" : "=f"(y) : "f"(x)); return y;
}
__device__ __forceinline__ float sigm(float x) {       // 1 MUFU
    return fmaf(0.5f, tanha(0.5f * x), 0.5f);
}
__device__ __forceinline__ uint32_t smem_u32(const void* p) {
    return (uint32_t)__cvta_generic_to_shared(p);
}
__device__ __forceinline__ uint32_t cluster_rank() {
    uint32_t r; asm("mov.u32 %0, %%cluster_ctarank;" : "=r"(r)); return r;
}
__device__ __forceinline__ uint32_t mapa_sh(uint32_t addr, uint32_t rank) {
    uint32_t r;
    asm("mapa.shared::cluster.u32 %0, %1, %2;" : "=r"(r) : "r"(addr), "r"(rank));
    return r;
}
__device__ __forceinline__ void mbar_init(uint32_t addr, uint32_t cnt) {
    asm volatile("mbarrier.init.shared.b64 [%0], %1;" :: "r"(addr), "r"(cnt) : "memory");
}
__device__ __forceinline__ void mbar_expect_tx(uint32_t addr, uint32_t bytes) {
    asm volatile("mbarrier.arrive.expect_tx.shared.b64 _, [%0], %1;"
                 :: "r"(addr), "r"(bytes) : "memory");
}
__device__ __forceinline__ void st_async_b32(uint32_t dst, float v, uint32_t mbar) {
    asm volatile("st.async.shared::cluster.mbarrier::complete_tx::bytes.b32 [%0], %1, [%2];"
                 :: "r"(dst), "r"(__float_as_uint(v)), "r"(mbar) : "memory");
}
__device__ __forceinline__ void mbar_wait_parity(uint32_t mbar, uint32_t parity) {
    asm volatile(
        "{\n\t.reg .pred P;\n"
        "W%=:\n\t"
        "mbarrier.try_wait.parity.acquire.cluster.shared::cta.b64 P, [%0], %1, 0x989680;\n\t"
        "@!P bra W%=;\n\t"
        "}" :: "r"(mbar), "r"(parity) : "memory");
}
__device__ __forceinline__ void cluster_sync_() {
    asm volatile("barrier.cluster.arrive.aligned;\n\tbarrier.cluster.wait.aligned;" ::: "memory");
}

// =====================================================================
// Kernel 1: char LSTM
// =====================================================================
#define CA_SW   (512 * 68)
#define CA_EMB  (128 * 64)
#define CA_HB   (32 * 64)
#define CA_SB   256
#define CHAR_SMEM_BYTES ((CA_SW + CA_EMB + CA_HB + CA_SB) * 4 + 512 * 4)

__global__ void __launch_bounds__(512, 1)
char_lstm_kernel(const int* __restrict__ ci_g, const int* __restrict__ clen,
                 const float* __restrict__ cemb_g,
                 const float* __restrict__ Wih, const float* __restrict__ Whh,
                 const float* __restrict__ bih, const float* __restrict__ bhh)
{
    extern __shared__ float smA[];
    float* sW    = smA;
    float* cemb  = sW + CA_SW;
    float* hbuf  = cemb + CA_EMB;
    float* sb    = hbuf + CA_HB;
    int*   scidx = (int*)(sb + CA_SB);

    const int tid = threadIdx.x;
    const int wbase = blockIdx.x * 32;

    for (int idx = tid; idx < 512 * 16; idx += 512) {
        int row = idx >> 4, k4 = idx & 15;
        const float* src = (row < 256) ? Wih + (size_t)row * 64 + k4 * 4
                                       : Whh + (size_t)(row - 256) * 64 + k4 * 4;
        *(float4*)&sW[row * 68 + k4 * 4] = *(const float4*)src;
    }
    for (int idx = tid; idx < 128 * 16; idx += 512) {
        int row = idx >> 4, k4 = idx & 15;
        *(float4*)&cemb[row * 64 + k4 * 4] = *(const float4*)(cemb_g + (size_t)row * 64 + k4 * 4);
    }
    if (tid < 256) sb[tid] = bih[tid] + bhh[tid];
    scidx[tid] = ci_g[(size_t)wbase * 16 + tid];
    for (int idx = tid; idx < CA_HB; idx += 512) hbuf[idx] = 0.f;

    const int rt = tid & 63, wt = tid >> 6, w0 = wt * 4;
    int len[4]; float cc[4];
    #pragma unroll
    for (int i = 0; i < 4; i++) { len[i] = clen[wbase + w0 + i]; cc[i] = 0.f; }
    __syncthreads();

    for (int t = 0; t < LC; t++) {
        int ci[4];
        #pragma unroll
        for (int i = 0; i < 4; i++) ci[i] = scidx[(w0 + i) * 16 + t];

        ull acc[4][4];
        #pragma unroll
        for (int i = 0; i < 4; i++)
            #pragma unroll
            for (int q = 0; q < 4; q++) acc[i][q] = 0ull;

        #pragma unroll
        for (int k4 = 0; k4 < 16; k4++) {
            ulonglong2 wv[4];
            #pragma unroll
            for (int q = 0; q < 4; q++)
                wv[q] = *(const ulonglong2*)&sW[(q * 64 + rt) * 68 + k4 * 4];
            #pragma unroll
            for (int i = 0; i < 4; i++) {
                ulonglong2 xv = *(const ulonglong2*)&cemb[ci[i] * 64 + k4 * 4];
                #pragma unroll
                for (int q = 0; q < 4; q++) {
                    acc[i][q] = ffma2(xv.x, wv[q].x, acc[i][q]);
                    acc[i][q] = ffma2(xv.y, wv[q].y, acc[i][q]);
                }
            }
        }
        #pragma unroll
        for (int k4 = 0; k4 < 16; k4++) {
            ulonglong2 wv[4];
            #pragma unroll
            for (int q = 0; q < 4; q++)
                wv[q] = *(const ulonglong2*)&sW[(256 + q * 64 + rt) * 68 + k4 * 4];
            #pragma unroll
            for (int i = 0; i < 4; i++) {
                ulonglong2 hv = *(const ulonglong2*)&hbuf[(w0 + i) * 64 + k4 * 4];
                #pragma unroll
                for (int q = 0; q < 4; q++) {
                    acc[i][q] = ffma2(hv.x, wv[q].x, acc[i][q]);
                    acc[i][q] = ffma2(hv.y, wv[q].y, acc[i][q]);
                }
            }
        }
        __syncthreads();

        float bI = sb[rt], bF = sb[64 + rt], bG = sb[128 + rt], bO = sb[192 + rt];
        #pragma unroll
        for (int i = 0; i < 4; i++) {
            float gi = f2sum(acc[i][0]) + bI;
            float gf = f2sum(acc[i][1]) + bF;
            float gG = f2sum(acc[i][2]) + bG;
            float go = f2sum(acc[i][3]) + bO;
            cc[i] = fmaf(sigm(gf), cc[i], sigm(gi) * tanha(gG));
            float h = sigm(go) * tanha(cc[i]);
            hbuf[(w0 + i) * 64 + rt] = h;
            if (t == len[i] - 1)
                g_char_feat[(size_t)(wbase + w0 + i) * 64 + rt] = h;
        }
        __syncthreads();
    }
}

// =====================================================================
// Kernel 2: gpre
// =====================================================================
#define BP 196
#define GPRE_SMEM_BYTES ((16 + 64) * BP * 4)

__global__ void __launch_bounds__(256, 1)
gpre_kernel(const int* __restrict__ widx, const float* __restrict__ wemb,
            const float* __restrict__ Wih,
            const float* __restrict__ bih, const float* __restrict__ bhh)
{
    extern __shared__ float smB[];
    float* sx = smB;
    float* sw = smB + 16 * BP;

    const int tid = threadIdx.x;
    const int t0 = blockIdx.x * 16;
    const int G0 = blockIdx.y * 64;

    for (int i = tid; i < 16 * 48; i += 256) {
        int tt = i / 48, k4 = i % 48;
        float4 v = (k4 < 32)
            ? *(const float4*)(wemb + (size_t)widx[t0 + tt] * 128 + k4 * 4)
            : *(const float4*)(g_char_feat + (size_t)(t0 + tt) * 64 + (k4 - 32) * 4);
        *(float4*)&sx[tt * BP + k4 * 4] = v;
    }
    for (int i = tid; i < 64 * 48; i += 256) {
        int r = i / 48, k4 = i % 48;
        *(float4*)&sw[r * BP + k4 * 4] = *(const float4*)(Wih + (size_t)(G0 + r) * 192 + k4 * 4);
    }
    __syncthreads();

    const int g = tid & 63, tq = tid >> 6;
    ull ax[4], ay[4];
    #pragma unroll
    for (int i = 0; i < 4; i++) { ax[i] = 0ull; ay[i] = 0ull; }

    #pragma unroll 4
    for (int k4 = 0; k4 < 48; k4++) {
        ulonglong2 wv = *(const ulonglong2*)&sw[g * BP + k4 * 4];
        #pragma unroll
        for (int it = 0; it < 4; it++) {
            ulonglong2 xv = *(const ulonglong2*)&sx[(tq * 4 + it) * BP + k4 * 4];
            ax[it] = ffma2(xv.x, wv.x, ax[it]);
            ay[it] = ffma2(xv.y, wv.y, ay[it]);
        }
    }
    float b = bih[G0 + g] + bhh[G0 + g];
    #pragma unroll
    for (int it = 0; it < 4; it++)
        g_gpre[(size_t)(t0 + tq * 4 + it) * 1024 + G0 + g] = f2sum(ax[it]) + f2sum(ay[it]) + b;
}

// =====================================================================
// Kernel 3: word LSTM. 8-CTA cluster, st.async tx barriers.
// Round-8 data path; interior loop unrolled by 2 with compile-time
// buffer/barrier offsets. Pair parity = m&1 for both half-steps.
// Pair-start gpre loads give the even step ~a full step of extra
// latency hiding. Tail (t = 8189, 8190, 8191) peeled.
// =====================================================================

// One recurrence step. SH_OFF: byte offset of h buffer to READ.
// ST_DOFF/ST_BOFF: subtracted from even-step store tables (dstE/brE).
#define WSTEP(BARADDR, PAR, G0_, G1_, G2_, G3_, SH_OFF, ST_DOFF, ST_BOFF, TIDX, DO_EXPECT, DO_STORE)  \
    do {                                                                                              \
        mbar_wait_parity((BARADDR), (PAR));                                                           \
        if ((DO_EXPECT) && tid == 0) mbar_expect_tx((BARADDR), 1024);                                 \
        const ulonglong2* hb_ = (const ulonglong2*)((const char*)sh + (SH_OFF));                      \
        ull a0_ = 0, a1_ = 0, a2_ = 0, a3_ = 0;                                                       \
        _Pragma("unroll")                                                                             \
        for (int m_ = 0; m_ < 8; m_++) {                                                              \
            ulonglong2 hv_ = hb_[oct + m_ * 8];                                                       \
            a0_ = ffma2(hv_.x, rw0[m_].x, a0_); a0_ = ffma2(hv_.y, rw0[m_].y, a0_);                   \
            a1_ = ffma2(hv_.x, rw1[m_].x, a1_); a1_ = ffma2(hv_.y, rw1[m_].y, a1_);                   \
            a2_ = ffma2(hv_.x, rw2[m_].x, a2_); a2_ = ffma2(hv_.y, rw2[m_].y, a2_);                   \
            a3_ = ffma2(hv_.x, rw3[m_].x, a3_); a3_ = ffma2(hv_.y, rw3[m_].y, a3_);                   \
        }                                                                                             \
        float s0_ = f2sum(a0_), s1_ = f2sum(a1_), s2_ = f2sum(a2_), s3_ = f2sum(a3_);                 \
        _Pragma("unroll")                                                                             \
        for (int off_ = 1; off_ <= 4; off_ <<= 1) {                                                   \
            s0_ += __shfl_xor_sync(0xFFFFFFFFu, s0_, off_);                                           \
            s1_ += __shfl_xor_sync(0xFFFFFFFFu, s1_, off_);                                           \
            s2_ += __shfl_xor_sync(0xFFFFFFFFu, s2_, off_);                                           \
            s3_ += __shfl_xor_sync(0xFFFFFFFFu, s3_, off_);                                           \
        }                                                                                             \
        s0_ += (G0_); s1_ += (G1_); s2_ += (G2_); s3_ += (G3_);                                       \
        c = fmaf(sigm(s1_), c, sigm(s0_) * tanha(s2_));                                               \
        float h_ = sigm(s3_) * tanha(c);                                                              \
        if (is_writer) {                                                                              \
            if (DO_STORE) {                                                                           \
                _Pragma("unroll")                                                                     \
                for (int dr_ = 0; dr_ < 8; dr_++)                                                     \
                    st_async_b32(dstE[dr_] - (ST_DOFF), h_, brE[dr_] - (ST_BOFF));                    \
            }                                                                                         \
            gwp[(size_t)(TIDX) * HW] = h_;                                                            \
        }                                                                                             \
    } while (0)

__global__ void __launch_bounds__(256, 1) __cluster_dims__(8, 1, 1)
word_lstm_kernel(const float* __restrict__ Whh)
{
    __shared__ float sh[2][256];                        // sh[1] = sh[0] + 1024 B
    __shared__ __align__(8) unsigned long long bar2[2]; // bar2[1] = bar2[0] + 8 B

    const int tid = threadIdx.x;
    const int jj  = tid >> 3;     // 0..31 h-unit
    const int oct = tid & 7;      // k octant
    const uint32_t rank = cluster_rank();
    const int uglob = (int)rank * 32 + jj;

    // weights: rw[q][m] covers gate row (q*256 + uglob), k = oct*4 + m*32
    ulonglong2 rw0[8], rw1[8], rw2[8], rw3[8];
    {
        const float* base = Whh + (size_t)uglob * 256 + oct * 4;
        #pragma unroll
        for (int m = 0; m < 8; m++) {
            rw0[m] = *(const ulonglong2*)(base + 0 * 65536 + m * 32);
            rw1[m] = *(const ulonglong2*)(base + 1 * 65536 + m * 32);
            rw2[m] = *(const ulonglong2*)(base + 2 * 65536 + m * 32);
            rw3[m] = *(const ulonglong2*)(base + 3 * 65536 + m * 32);
        }
    }

    sh[0][tid] = 0.f;
    sh[1][tid] = 0.f;
    const uint32_t locb0 = smem_u32(&bar2[0]);
    const uint32_t locb1 = smem_u32(&bar2[1]);
    if (tid == 0) {
        mbar_init(locb0, 1);
        mbar_init(locb1, 1);
        mbar_expect_tx(locb0, 1024);
        mbar_expect_tx(locb1, 1024);
    }
    __syncthreads();
    cluster_sync_();

    // even-step tables (write sh[1]/bar1); odd step derives by -1024 / -8
    uint32_t dstE[8], brE[8];
    {
        uint32_t aE = smem_u32(&sh[1][uglob]);
        #pragma unroll
        for (int dr = 0; dr < 8; dr++) {
            dstE[dr] = mapa_sh(aE, dr);
            brE[dr]  = mapa_sh(locb1, dr);
        }
    }

    float c = 0.f;
    const bool is_writer = (oct == 0);
    float* const gwp = g_wh + uglob;

    // ---------- t = 0 (no wait; h_prev = 0, c_prev = 0; even: sh[1]/bar1) ----------
    if (is_writer) {
        const float* gpp0 = g_gpre;
        float gp0 = gpp0[uglob], gp2 = gpp0[512 + uglob], gp3 = gpp0[768 + uglob];
        c = sigm(gp0) * tanha(gp2);
        float h = sigm(gp3) * tanha(c);
        #pragma unroll
        for (int dr = 0; dr < 8; dr++) st_async_b32(dstE[dr], h, brE[dr]);
        gwp[0] = h;
    }

    // ---------- interior pairs: m = 0..4093 covers t = 1..8188 ----------
    const float* gpp = g_gpre + 1024 + uglob;   // points at t = 1 row
    float A0 = 0.f, A1 = 0.f, A2 = 0.f, A3 = 0.f;   // gp for odd step t=2m+1
    float B0 = 0.f, B1 = 0.f, B2 = 0.f, B3 = 0.f;   // gp for even step t=2m+2
    if (is_writer) {
        A0 = gpp[0];    A1 = gpp[256];  A2 = gpp[512];  A3 = gpp[768];
        B0 = gpp[1024]; B1 = gpp[1280]; B2 = gpp[1536]; B3 = gpp[1792];
    }

    for (int m = 0; m < 4094; m++) {
        // prefetch next pair (t = 2m+3, 2m+4) — valid up to t=8190 at m=4093
        float N0 = 0.f, N1 = 0.f, N2 = 0.f, N3 = 0.f;
        float M0 = 0.f, M1 = 0.f, M2 = 0.f, M3 = 0.f;
        if (is_writer) {
            const float* np = gpp + 2048;
            N0 = np[0];    N1 = np[256];  N2 = np[512];  N3 = np[768];
            M0 = np[1024]; M1 = np[1280]; M2 = np[1536]; M3 = np[1792];
        }
        const uint32_t ph = (uint32_t)m & 1u;

        // t odd (b=1): wait bar1, read sh[1], store sh[0]/bar0
        WSTEP(locb1, ph, A0, A1, A2, A3, 1024u, 1024u, 8u, 2 * m + 1, 1, 1);
        // t even (b=0): wait bar0, read sh[0], store sh[1]/bar1
        WSTEP(locb0, ph, B0, B1, B2, B3, 0u, 0u, 0u, 2 * m + 2, 1, 1);

        A0 = N0; A1 = N1; A2 = N2; A3 = N3;
        B0 = M0; B1 = M1; B2 = M2; B3 = M3;
        gpp += 2048;
    }

    // ---------- tail: t = 8189 (odd), 8190 (even), 8191 (odd, no store) ----------
    // After loop: A = gp(t=8189), B = gp(t=8190); ph = 4094 & 1 = 0.
    {
        float F0 = 0.f, F1 = 0.f, F2 = 0.f, F3 = 0.f;   // gp for t = 8191
        if (is_writer) {
            const float* fp = gpp + 2048;
            F0 = fp[0]; F1 = fp[256]; F2 = fp[512]; F3 = fp[768];
        }
        WSTEP(locb1, 0u, A0, A1, A2, A3, 1024u, 1024u, 8u, 8189, 1, 1);
        WSTEP(locb0, 0u, B0, B1, B2, B3, 0u, 0u, 0u, 8190, 1, 1);
        // t = 8191: wait bar1 parity 1, no expect re-arm, no fabric store
        WSTEP(locb1, 1u, F0, F1, F2, F3, 1024u, 0u, 0u, 8191, 0, 0);
    }
}

// =====================================================================
// Kernel 4: tag head + log_softmax. 256 blocks x 32 tokens.
// =====================================================================
#define TAG_SW   (256 * 64)
#define TAG_SMEM_BYTES ((TAG_SW + 64) * 4)

__global__ void __launch_bounds__(256, 1)
tag_kernel(const float* __restrict__ tagW, const float* __restrict__ tagb,
           float* __restrict__ out)
{
    extern __shared__ float smT[];
    float* sw = smT;
    float* sb = smT + TAG_SW;

    const int tid = threadIdx.x;
    const int lane = tid & 31, warp = tid >> 5;

    for (int i = tid; i < TAG_SW; i += 256) sw[i] = 0.f;
    if (tid < 64) sb[tid] = (tid < TAGS) ? tagb[tid] : 0.f;
    __syncthreads();
    for (int i = tid; i < TAGS * 256; i += 256) {
        int tg = i >> 8, k = i & 255;
        sw[k * 64 + tg] = tagW[i];
    }
    __syncthreads();

    const bool v1 = (32 + lane) < TAGS;

    #pragma unroll 1
    for (int it = 0; it < 4; it++) {
        const int token = blockIdx.x * 32 + it * 8 + warp;
        const float4* hp4 = (const float4*)(g_wh + (size_t)token * 256);

        float a0 = 0.f, a1 = 0.f;
        #pragma unroll 8
        for (int k4 = 0; k4 < 64; k4++) {
            float4 h = hp4[k4];
            const float* p = sw + k4 * 256 + lane;
            a0 = fmaf(h.x, p[0],   a0);  a1 = fmaf(h.x, p[32],  a1);
            a0 = fmaf(h.y, p[64],  a0);  a1 = fmaf(h.y, p[96],  a1);
            a0 = fmaf(h.z, p[128], a0);  a1 = fmaf(h.z, p[160], a1);
            a0 = fmaf(h.w, p[192], a0);  a1 = fmaf(h.w, p[224], a1);
        }
        a0 += sb[lane];
        a1 += sb[32 + lane];

        float m = fmaxf(a0, v1 ? a1 : -3.4e38f);
        #pragma unroll
        for (int off = 16; off; off >>= 1)
            m = fmaxf(m, __shfl_xor_sync(0xFFFFFFFFu, m, off));
        float e = __expf(a0 - m) + (v1 ? __expf(a1 - m) : 0.f);
        #pragma unroll
        for (int off = 16; off; off >>= 1)
            e += __shfl_xor_sync(0xFFFFFFFFu, e, off);
        float ls = __logf(e);

        out[(size_t)token * TAGS + lane] = a0 - m - ls;
        if (v1) out[(size_t)token * TAGS + 32 + lane] = a1 - m - ls;
    }
}

// =====================================================================
extern "C" void kernel_launch(void* const* d_in, const int* in_sizes, int n_in,
                              void* d_out, int out_size)
{
    const int*   word_idxs = (const int*)d_in[0];
    const int*   char_idxs = (const int*)d_in[1];
    const int*   char_lens = (const int*)d_in[2];
    const float* char_emb  = (const float*)d_in[3];
    const float* char_Wih  = (const float*)d_in[4];
    const float* char_Whh  = (const float*)d_in[5];
    const float* char_bih  = (const float*)d_in[6];
    const float* char_bhh  = (const float*)d_in[7];
    const float* word_emb  = (const float*)d_in[8];
    const float* word_Wih  = (const float*)d_in[9];
    const float* word_Whh  = (const float*)d_in[10];
    const float* word_bih  = (const float*)d_in[11];
    const float* word_bhh  = (const float*)d_in[12];
    const float* tag_W     = (const float*)d_in[13];
    const float* tag_b     = (const float*)d_in[14];
    float* out = (float*)d_out;

    cudaFuncSetAttribute(char_lstm_kernel,
                         cudaFuncAttributeMaxDynamicSharedMemorySize, CHAR_SMEM_BYTES);
    cudaFuncSetAttribute(gpre_kernel,
                         cudaFuncAttributeMaxDynamicSharedMemorySize, GPRE_SMEM_BYTES);
    cudaFuncSetAttribute(tag_kernel,
                         cudaFuncAttributeMaxDynamicSharedMemorySize, TAG_SMEM_BYTES);

    char_lstm_kernel<<<256, 512, CHAR_SMEM_BYTES>>>(
        char_idxs, char_lens, char_emb, char_Wih, char_Whh, char_bih, char_bhh);

    dim3 gb(S / 16, 1024 / 64);
    gpre_kernel<<<gb, 256, GPRE_SMEM_BYTES>>>(
        word_idxs, word_emb, word_Wih, word_bih, word_bhh);

    word_lstm_kernel<<<8, 256>>>(word_Whh);

    tag_kernel<<<S / 32, 256, TAG_SMEM_BYTES>>>(tag_W, tag_b, out);
}

// round 11
// speedup vs baseline: 1.6714x; 1.0285x over previous
#include <cuda_runtime.h>
#include <cstdint>
#include <cstddef>

#define S     8192
#define LC    16
#define CH    64
#define HW    256
#define TAGS  50

typedef unsigned long long ull;

// ---------------- device scratch ----------------
__device__ __align__(256) float g_char_feat[S * CH];        // 2 MB
__device__ __align__(256) float g_gpre[(size_t)S * 4 * HW]; // 32 MB
__device__ __align__(256) float g_wh[(size_t)S * HW];       // 8 MB

// ---------------- helpers ----------------
__device__ __forceinline__ ull ffma2(ull a, ull b, ull c) {
    ull d;
    asm("fma.rn.f32x2 %0, %1, %2, %3;" : "=l"(d) : "l"(a), "l"(b), "l"(c));
    return d;
}
__device__ __forceinline__ float f2sum(ull a) {
    float lo = __uint_as_float((unsigned)(a & 0xffffffffull));
    float hi = __uint_as_float((unsigned)(a >> 32));
    return lo + hi;
}
__device__ __forceinline__ float tanha(float x) {
    float y; asm("tanh.approx.f32 %0, %1;" : "=f"(y) : "f"(x)); return y;
}
__device__ __forceinline__ float sigm(float x) {       // 1 MUFU
    return fmaf(0.5f, tanha(0.5f * x), 0.5f);
}
__device__ __forceinline__ uint32_t smem_u32(const void* p) {
    return (uint32_t)__cvta_generic_to_shared(p);
}
__device__ __forceinline__ uint32_t cluster_rank() {
    uint32_t r; asm("mov.u32 %0, %%cluster_ctarank;" : "=r"(r)); return r;
}
__device__ __forceinline__ uint32_t mapa_sh(uint32_t addr, uint32_t rank) {
    uint32_t r;
    asm("mapa.shared::cluster.u32 %0, %1, %2;" : "=r"(r) : "r"(addr), "r"(rank));
    return r;
}
__device__ __forceinline__ void mbar_init(uint32_t addr, uint32_t cnt) {
    asm volatile("mbarrier.init.shared.b64 [%0], %1;" :: "r"(addr), "r"(cnt) : "memory");
}
__device__ __forceinline__ void mbar_expect_tx(uint32_t addr, uint32_t bytes) {
    asm volatile("mbarrier.arrive.expect_tx.shared.b64 _, [%0], %1;"
                 :: "r"(addr), "r"(bytes) : "memory");
}
__device__ __forceinline__ void st_async_b32(uint32_t dst, float v, uint32_t mbar) {
    asm volatile("st.async.shared::cluster.mbarrier::complete_tx::bytes.b32 [%0], %1, [%2];"
                 :: "r"(dst), "r"(__float_as_uint(v)), "r"(mbar) : "memory");
}
__device__ __forceinline__ void mbar_wait_parity(uint32_t mbar, uint32_t parity) {
    asm volatile(
        "{\n\t.reg .pred P;\n"
        "W%=:\n\t"
        "mbarrier.try_wait.parity.acquire.cluster.shared::cta.b64 P, [%0], %1, 0x989680;\n\t"
        "@!P bra W%=;\n\t"
        "}" :: "r"(mbar), "r"(parity) : "memory");
}
__device__ __forceinline__ void cluster_sync_() {
    asm volatile("barrier.cluster.arrive.aligned;\n\tbarrier.cluster.wait.aligned;" ::: "memory");
}

// =====================================================================
// Kernel 1: char LSTM
// =====================================================================
#define CA_SW   (512 * 68)
#define CA_EMB  (128 * 64)
#define CA_HB   (32 * 64)
#define CA_SB   256
#define CHAR_SMEM_BYTES ((CA_SW + CA_EMB + CA_HB + CA_SB) * 4 + 512 * 4)

__global__ void __launch_bounds__(512, 1)
char_lstm_kernel(const int* __restrict__ ci_g, const int* __restrict__ clen,
                 const float* __restrict__ cemb_g,
                 const float* __restrict__ Wih, const float* __restrict__ Whh,
                 const float* __restrict__ bih, const float* __restrict__ bhh)
{
    extern __shared__ float smA[];
    float* sW    = smA;
    float* cemb  = sW + CA_SW;
    float* hbuf  = cemb + CA_EMB;
    float* sb    = hbuf + CA_HB;
    int*   scidx = (int*)(sb + CA_SB);

    const int tid = threadIdx.x;
    const int wbase = blockIdx.x * 32;

    for (int idx = tid; idx < 512 * 16; idx += 512) {
        int row = idx >> 4, k4 = idx & 15;
        const float* src = (row < 256) ? Wih + (size_t)row * 64 + k4 * 4
                                       : Whh + (size_t)(row - 256) * 64 + k4 * 4;
        *(float4*)&sW[row * 68 + k4 * 4] = *(const float4*)src;
    }
    for (int idx = tid; idx < 128 * 16; idx += 512) {
        int row = idx >> 4, k4 = idx & 15;
        *(float4*)&cemb[row * 64 + k4 * 4] = *(const float4*)(cemb_g + (size_t)row * 64 + k4 * 4);
    }
    if (tid < 256) sb[tid] = bih[tid] + bhh[tid];
    scidx[tid] = ci_g[(size_t)wbase * 16 + tid];
    for (int idx = tid; idx < CA_HB; idx += 512) hbuf[idx] = 0.f;

    const int rt = tid & 63, wt = tid >> 6, w0 = wt * 4;
    int len[4]; float cc[4];
    #pragma unroll
    for (int i = 0; i < 4; i++) { len[i] = clen[wbase + w0 + i]; cc[i] = 0.f; }
    __syncthreads();

    for (int t = 0; t < LC; t++) {
        int ci[4];
        #pragma unroll
        for (int i = 0; i < 4; i++) ci[i] = scidx[(w0 + i) * 16 + t];

        ull acc[4][4];
        #pragma unroll
        for (int i = 0; i < 4; i++)
            #pragma unroll
            for (int q = 0; q < 4; q++) acc[i][q] = 0ull;

        #pragma unroll
        for (int k4 = 0; k4 < 16; k4++) {
            ulonglong2 wv[4];
            #pragma unroll
            for (int q = 0; q < 4; q++)
                wv[q] = *(const ulonglong2*)&sW[(q * 64 + rt) * 68 + k4 * 4];
            #pragma unroll
            for (int i = 0; i < 4; i++) {
                ulonglong2 xv = *(const ulonglong2*)&cemb[ci[i] * 64 + k4 * 4];
                #pragma unroll
                for (int q = 0; q < 4; q++) {
                    acc[i][q] = ffma2(xv.x, wv[q].x, acc[i][q]);
                    acc[i][q] = ffma2(xv.y, wv[q].y, acc[i][q]);
                }
            }
        }
        #pragma unroll
        for (int k4 = 0; k4 < 16; k4++) {
            ulonglong2 wv[4];
            #pragma unroll
            for (int q = 0; q < 4; q++)
                wv[q] = *(const ulonglong2*)&sW[(256 + q * 64 + rt) * 68 + k4 * 4];
            #pragma unroll
            for (int i = 0; i < 4; i++) {
                ulonglong2 hv = *(const ulonglong2*)&hbuf[(w0 + i) * 64 + k4 * 4];
                #pragma unroll
                for (int q = 0; q < 4; q++) {
                    acc[i][q] = ffma2(hv.x, wv[q].x, acc[i][q]);
                    acc[i][q] = ffma2(hv.y, wv[q].y, acc[i][q]);
                }
            }
        }
        __syncthreads();

        float bI = sb[rt], bF = sb[64 + rt], bG = sb[128 + rt], bO = sb[192 + rt];
        #pragma unroll
        for (int i = 0; i < 4; i++) {
            float gi = f2sum(acc[i][0]) + bI;
            float gf = f2sum(acc[i][1]) + bF;
            float gG = f2sum(acc[i][2]) + bG;
            float go = f2sum(acc[i][3]) + bO;
            cc[i] = fmaf(sigm(gf), cc[i], sigm(gi) * tanha(gG));
            float h = sigm(go) * tanha(cc[i]);
            hbuf[(w0 + i) * 64 + rt] = h;
            if (t == len[i] - 1)
                g_char_feat[(size_t)(wbase + w0 + i) * 64 + rt] = h;
        }
        __syncthreads();
    }
}

// =====================================================================
// Kernel 2: gpre
// =====================================================================
#define BP 196
#define GPRE_SMEM_BYTES ((16 + 64) * BP * 4)

__global__ void __launch_bounds__(256, 1)
gpre_kernel(const int* __restrict__ widx, const float* __restrict__ wemb,
            const float* __restrict__ Wih,
            const float* __restrict__ bih, const float* __restrict__ bhh)
{
    extern __shared__ float smB[];
    float* sx = smB;
    float* sw = smB + 16 * BP;

    const int tid = threadIdx.x;
    const int t0 = blockIdx.x * 16;
    const int G0 = blockIdx.y * 64;

    for (int i = tid; i < 16 * 48; i += 256) {
        int tt = i / 48, k4 = i % 48;
        float4 v = (k4 < 32)
            ? *(const float4*)(wemb + (size_t)widx[t0 + tt] * 128 + k4 * 4)
            : *(const float4*)(g_char_feat + (size_t)(t0 + tt) * 64 + (k4 - 32) * 4);
        *(float4*)&sx[tt * BP + k4 * 4] = v;
    }
    for (int i = tid; i < 64 * 48; i += 256) {
        int r = i / 48, k4 = i % 48;
        *(float4*)&sw[r * BP + k4 * 4] = *(const float4*)(Wih + (size_t)(G0 + r) * 192 + k4 * 4);
    }
    __syncthreads();

    const int g = tid & 63, tq = tid >> 6;
    ull ax[4], ay[4];
    #pragma unroll
    for (int i = 0; i < 4; i++) { ax[i] = 0ull; ay[i] = 0ull; }

    #pragma unroll 4
    for (int k4 = 0; k4 < 48; k4++) {
        ulonglong2 wv = *(const ulonglong2*)&sw[g * BP + k4 * 4];
        #pragma unroll
        for (int it = 0; it < 4; it++) {
            ulonglong2 xv = *(const ulonglong2*)&sx[(tq * 4 + it) * BP + k4 * 4];
            ax[it] = ffma2(xv.x, wv.x, ax[it]);
            ay[it] = ffma2(xv.y, wv.y, ay[it]);
        }
    }
    float b = bih[G0 + g] + bhh[G0 + g];
    #pragma unroll
    for (int it = 0; it < 4; it++)
        g_gpre[(size_t)(t0 + tq * 4 + it) * 1024 + G0 + g] = f2sum(ax[it]) + f2sum(ay[it]) + b;
}

// =====================================================================
// Kernel 3: word LSTM. 8-CTA cluster, st.async tx barriers.
// Round-10 structure (unroll-2, peeled), with the 8-dest broadcast
// spread across octant lanes: after the shfl_xor reduction every lane
// of an oct-group holds the full gate sums; every lane loads its gpre
// so h is computed (redundantly but identically) on all 8 lanes, and
// lane (jj, oct) sends h(unit jj) to dest CTA oct only -> ONE warp-wide
// st.async instruction replaces 8 sequential predicated ones.
// Per-dest tx unchanged: 8 src CTAs x 32 units x 4 B = 1024 B.
// =====================================================================

#define WSTEP(BARADDR, PAR, G0_, G1_, G2_, G3_, SH_OFF, ST_DOFF, ST_BOFF, TIDX, DO_EXPECT, DO_STORE)  \
    do {                                                                                              \
        mbar_wait_parity((BARADDR), (PAR));                                                           \
        if ((DO_EXPECT) && tid == 0) mbar_expect_tx((BARADDR), 1024);                                 \
        const ulonglong2* hb_ = (const ulonglong2*)((const char*)sh + (SH_OFF));                      \
        ull a0_ = 0, a1_ = 0, a2_ = 0, a3_ = 0;                                                       \
        _Pragma("unroll")                                                                             \
        for (int m_ = 0; m_ < 8; m_++) {                                                              \
            ulonglong2 hv_ = hb_[oct + m_ * 8];                                                       \
            a0_ = ffma2(hv_.x, rw0[m_].x, a0_); a0_ = ffma2(hv_.y, rw0[m_].y, a0_);                   \
            a1_ = ffma2(hv_.x, rw1[m_].x, a1_); a1_ = ffma2(hv_.y, rw1[m_].y, a1_);                   \
            a2_ = ffma2(hv_.x, rw2[m_].x, a2_); a2_ = ffma2(hv_.y, rw2[m_].y, a2_);                   \
            a3_ = ffma2(hv_.x, rw3[m_].x, a3_); a3_ = ffma2(hv_.y, rw3[m_].y, a3_);                   \
        }                                                                                             \
        float s0_ = f2sum(a0_), s1_ = f2sum(a1_), s2_ = f2sum(a2_), s3_ = f2sum(a3_);                 \
        _Pragma("unroll")                                                                             \
        for (int off_ = 1; off_ <= 4; off_ <<= 1) {                                                   \
            s0_ += __shfl_xor_sync(0xFFFFFFFFu, s0_, off_);                                           \
            s1_ += __shfl_xor_sync(0xFFFFFFFFu, s1_, off_);                                           \
            s2_ += __shfl_xor_sync(0xFFFFFFFFu, s2_, off_);                                           \
            s3_ += __shfl_xor_sync(0xFFFFFFFFu, s3_, off_);                                           \
        }                                                                                             \
        s0_ += (G0_); s1_ += (G1_); s2_ += (G2_); s3_ += (G3_);                                       \
        c = fmaf(sigm(s1_), c, sigm(s0_) * tanha(s2_));                                               \
        float h_ = sigm(s3_) * tanha(c);                                                              \
        if (DO_STORE)                                                                                 \
            st_async_b32(dst_my - (ST_DOFF), h_, bar_my - (ST_BOFF));                                 \
        if (is_writer)                                                                                \
            gwp[(size_t)(TIDX) * HW] = h_;                                                            \
    } while (0)

__global__ void __launch_bounds__(256, 1) __cluster_dims__(8, 1, 1)
word_lstm_kernel(const float* __restrict__ Whh)
{
    __shared__ float sh[2][256];                        // sh[1] = sh[0] + 1024 B
    __shared__ __align__(8) unsigned long long bar2[2]; // bar2[1] = bar2[0] + 8 B

    const int tid = threadIdx.x;
    const int jj  = tid >> 3;     // 0..31 h-unit
    const int oct = tid & 7;      // k octant == this lane's dest CTA
    const uint32_t rank = cluster_rank();
    const int uglob = (int)rank * 32 + jj;

    // weights: rw[q][m] covers gate row (q*256 + uglob), k = oct*4 + m*32
    ulonglong2 rw0[8], rw1[8], rw2[8], rw3[8];
    {
        const float* base = Whh + (size_t)uglob * 256 + oct * 4;
        #pragma unroll
        for (int m = 0; m < 8; m++) {
            rw0[m] = *(const ulonglong2*)(base + 0 * 65536 + m * 32);
            rw1[m] = *(const ulonglong2*)(base + 1 * 65536 + m * 32);
            rw2[m] = *(const ulonglong2*)(base + 2 * 65536 + m * 32);
            rw3[m] = *(const ulonglong2*)(base + 3 * 65536 + m * 32);
        }
    }

    sh[0][tid] = 0.f;
    sh[1][tid] = 0.f;
    const uint32_t locb0 = smem_u32(&bar2[0]);
    const uint32_t locb1 = smem_u32(&bar2[1]);
    if (tid == 0) {
        mbar_init(locb0, 1);
        mbar_init(locb1, 1);
        mbar_expect_tx(locb0, 1024);
        mbar_expect_tx(locb1, 1024);
    }
    __syncthreads();
    cluster_sync_();

    // per-lane store target: unit uglob's slot / bar1 in dest CTA = oct
    // (even step; odd step derives by -1024 / -8)
    const uint32_t dst_my = mapa_sh(smem_u32(&sh[1][uglob]), (uint32_t)oct);
    const uint32_t bar_my = mapa_sh(locb1, (uint32_t)oct);

    float c = 0.f;
    const bool is_writer = (oct == 0);
    float* const gwp = g_wh + uglob;

    // ---------- t = 0 (no wait; h_prev = 0, c_prev = 0; all lanes) ----------
    {
        const float* gpp0 = g_gpre + uglob;
        float gp0 = gpp0[0], gp2 = gpp0[512], gp3 = gpp0[768];
        c = sigm(gp0) * tanha(gp2);
        float h = sigm(gp3) * tanha(c);
        st_async_b32(dst_my, h, bar_my);
        if (is_writer) gwp[0] = h;
    }

    // ---------- interior pairs: m = 0..4093 covers t = 1..8188 ----------
    const float* gpp = g_gpre + 1024 + uglob;   // points at t = 1 row
    float A0, A1, A2, A3;   // gp for odd step t=2m+1
    float B0, B1, B2, B3;   // gp for even step t=2m+2
    A0 = gpp[0];    A1 = gpp[256];  A2 = gpp[512];  A3 = gpp[768];
    B0 = gpp[1024]; B1 = gpp[1280]; B2 = gpp[1536]; B3 = gpp[1792];

    for (int m = 0; m < 4094; m++) {
        // prefetch next pair (t = 2m+3, 2m+4)
        const float* np = gpp + 2048;
        float N0 = np[0],    N1 = np[256],  N2 = np[512],  N3 = np[768];
        float M0 = np[1024], M1 = np[1280], M2 = np[1536], M3 = np[1792];
        const uint32_t ph = (uint32_t)m & 1u;

        // t odd (b=1): wait bar1, read sh[1], store sh[0]/bar0
        WSTEP(locb1, ph, A0, A1, A2, A3, 1024u, 1024u, 8u, 2 * m + 1, 1, 1);
        // t even (b=0): wait bar0, read sh[0], store sh[1]/bar1
        WSTEP(locb0, ph, B0, B1, B2, B3, 0u, 0u, 0u, 2 * m + 2, 1, 1);

        A0 = N0; A1 = N1; A2 = N2; A3 = N3;
        B0 = M0; B1 = M1; B2 = M2; B3 = M3;
        gpp += 2048;
    }

    // ---------- tail: t = 8189 (odd), 8190 (even), 8191 (odd, no store) ----------
    {
        const float* fp = gpp + 2048;
        float F0 = fp[0], F1 = fp[256], F2 = fp[512], F3 = fp[768];
        WSTEP(locb1, 0u, A0, A1, A2, A3, 1024u, 1024u, 8u, 8189, 1, 1);
        WSTEP(locb0, 0u, B0, B1, B2, B3, 0u, 0u, 0u, 8190, 1, 1);
        WSTEP(locb1, 1u, F0, F1, F2, F3, 1024u, 0u, 0u, 8191, 0, 0);
    }
}

// =====================================================================
// Kernel 4: tag head + log_softmax. 256 blocks x 32 tokens.
// =====================================================================
#define TAG_SW   (256 * 64)
#define TAG_SMEM_BYTES ((TAG_SW + 64) * 4)

__global__ void __launch_bounds__(256, 1)
tag_kernel(const float* __restrict__ tagW, const float* __restrict__ tagb,
           float* __restrict__ out)
{
    extern __shared__ float smT[];
    float* sw = smT;
    float* sb = smT + TAG_SW;

    const int tid = threadIdx.x;
    const int lane = tid & 31, warp = tid >> 5;

    for (int i = tid; i < TAG_SW; i += 256) sw[i] = 0.f;
    if (tid < 64) sb[tid] = (tid < TAGS) ? tagb[tid] : 0.f;
    __syncthreads();
    for (int i = tid; i < TAGS * 256; i += 256) {
        int tg = i >> 8, k = i & 255;
        sw[k * 64 + tg] = tagW[i];
    }
    __syncthreads();

    const bool v1 = (32 + lane) < TAGS;

    #pragma unroll 1
    for (int it = 0; it < 4; it++) {
        const int token = blockIdx.x * 32 + it * 8 + warp;
        const float4* hp4 = (const float4*)(g_wh + (size_t)token * 256);

        float a0 = 0.f, a1 = 0.f;
        #pragma unroll 8
        for (int k4 = 0; k4 < 64; k4++) {
            float4 h = hp4[k4];
            const float* p = sw + k4 * 256 + lane;
            a0 = fmaf(h.x, p[0],   a0);  a1 = fmaf(h.x, p[32],  a1);
            a0 = fmaf(h.y, p[64],  a0);  a1 = fmaf(h.y, p[96],  a1);
            a0 = fmaf(h.z, p[128], a0);  a1 = fmaf(h.z, p[160], a1);
            a0 = fmaf(h.w, p[192], a0);  a1 = fmaf(h.w, p[224], a1);
        }
        a0 += sb[lane];
        a1 += sb[32 + lane];

        float m = fmaxf(a0, v1 ? a1 : -3.4e38f);
        #pragma unroll
        for (int off = 16; off; off >>= 1)
            m = fmaxf(m, __shfl_xor_sync(0xFFFFFFFFu, m, off));
        float e = __expf(a0 - m) + (v1 ? __expf(a1 - m) : 0.f);
        #pragma unroll
        for (int off = 16; off; off >>= 1)
            e += __shfl_xor_sync(0xFFFFFFFFu, e, off);
        float ls = __logf(e);

        out[(size_t)token * TAGS + lane] = a0 - m - ls;
        if (v1) out[(size_t)token * TAGS + 32 + lane] = a1 - m - ls;
    }
}

// =====================================================================
extern "C" void kernel_launch(void* const* d_in, const int* in_sizes, int n_in,
                              void* d_out, int out_size)
{
    const int*   word_idxs = (const int*)d_in[0];
    const int*   char_idxs = (const int*)d_in[1];
    const int*   char_lens = (const int*)d_in[2];
    const float* char_emb  = (const float*)d_in[3];
    const float* char_Wih  = (const float*)d_in[4];
    const float* char_Whh  = (const float*)d_in[5];
    const float* char_bih  = (const float*)d_in[6];
    const float* char_bhh  = (const float*)d_in[7];
    const float* word_emb  = (const float*)d_in[8];
    const float* word_Wih  = (const float*)d_in[9];
    const float* word_Whh  = (const float*)d_in[10];
    const float* word_bih  = (const float*)d_in[11];
    const float* word_bhh  = (const float*)d_in[12];
    const float* tag_W     = (const float*)d_in[13];
    const float* tag_b     = (const float*)d_in[14];
    float* out = (float*)d_out;

    cudaFuncSetAttribute(char_lstm_kernel,
                         cudaFuncAttributeMaxDynamicSharedMemorySize, CHAR_SMEM_BYTES);
    cudaFuncSetAttribute(gpre_kernel,
                         cudaFuncAttributeMaxDynamicSharedMemorySize, GPRE_SMEM_BYTES);
    cudaFuncSetAttribute(tag_kernel,
                         cudaFuncAttributeMaxDynamicSharedMemorySize, TAG_SMEM_BYTES);

    char_lstm_kernel<<<256, 512, CHAR_SMEM_BYTES>>>(
        char_idxs, char_lens, char_emb, char_Wih, char_Whh, char_bih, char_bhh);

    dim3 gb(S / 16, 1024 / 64);
    gpre_kernel<<<gb, 256, GPRE_SMEM_BYTES>>>(
        word_idxs, word_emb, word_Wih, word_bih, word_bhh);

    word_lstm_kernel<<<8, 256>>>(word_Whh);

    tag_kernel<<<S / 32, 256, TAG_SMEM_BYTES>>>(tag_W, tag_b, out);
}

// round 12
// speedup vs baseline: 1.7061x; 1.0208x over previous
#include <cuda_runtime.h>
#include <cstdint>
#include <cstddef>

#define S     8192
#define LC    16
#define CH    64
#define HW    256
#define TAGS  50

typedef unsigned long long ull;

// ---------------- device scratch ----------------
__device__ __align__(256) float g_char_feat[S * CH];        // 2 MB
__device__ __align__(256) float g_gpre[(size_t)S * 4 * HW]; // 32 MB
__device__ __align__(256) float g_wh[(size_t)S * HW];       // 8 MB

// ---------------- helpers ----------------
__device__ __forceinline__ ull ffma2(ull a, ull b, ull c) {
    ull d;
    asm("fma.rn.f32x2 %0, %1, %2, %3;" : "=l"(d) : "l"(a), "l"(b), "l"(c));
    return d;
}
__device__ __forceinline__ ull packf2(float lo, float hi) {
    ull r;
    asm("mov.b64 %0, {%1, %2};" : "=l"(r) : "f"(lo), "f"(hi));
    return r;
}
__device__ __forceinline__ float f2sum(ull a) {
    float lo = __uint_as_float((unsigned)(a & 0xffffffffull));
    float hi = __uint_as_float((unsigned)(a >> 32));
    return lo + hi;
}
__device__ __forceinline__ float tanha(float x) {
    float y; asm("tanh.approx.f32 %0, %1;" : "=f"(y) : "f"(x)); return y;
}
__device__ __forceinline__ float sigm(float x) {       // 1 MUFU
    return fmaf(0.5f, tanha(0.5f * x), 0.5f);
}
__device__ __forceinline__ uint32_t smem_u32(const void* p) {
    return (uint32_t)__cvta_generic_to_shared(p);
}
__device__ __forceinline__ uint32_t cluster_rank() {
    uint32_t r; asm("mov.u32 %0, %%cluster_ctarank;" : "=r"(r)); return r;
}
__device__ __forceinline__ uint32_t mapa_sh(uint32_t addr, uint32_t rank) {
    uint32_t r;
    asm("mapa.shared::cluster.u32 %0, %1, %2;" : "=r"(r) : "r"(addr), "r"(rank));
    return r;
}
__device__ __forceinline__ void mbar_init(uint32_t addr, uint32_t cnt) {
    asm volatile("mbarrier.init.shared.b64 [%0], %1;" :: "r"(addr), "r"(cnt) : "memory");
}
__device__ __forceinline__ void mbar_expect_tx(uint32_t addr, uint32_t bytes) {
    asm volatile("mbarrier.arrive.expect_tx.shared.b64 _, [%0], %1;"
                 :: "r"(addr), "r"(bytes) : "memory");
}
__device__ __forceinline__ void st_async_b32(uint32_t dst, float v, uint32_t mbar) {
    asm volatile("st.async.shared::cluster.mbarrier::complete_tx::bytes.b32 [%0], %1, [%2];"
                 :: "r"(dst), "r"(__float_as_uint(v)), "r"(mbar) : "memory");
}
__device__ __forceinline__ void mbar_wait_parity(uint32_t mbar, uint32_t parity) {
    asm volatile(
        "{\n\t.reg .pred P;\n"
        "W%=:\n\t"
        "mbarrier.try_wait.parity.acquire.cluster.shared::cta.b64 P, [%0], %1, 0x989680;\n\t"
        "@!P bra W%=;\n\t"
        "}" :: "r"(mbar), "r"(parity) : "memory");
}
__device__ __forceinline__ void cluster_sync_() {
    asm volatile("barrier.cluster.arrive.aligned;\n\tbarrier.cluster.wait.aligned;" ::: "memory");
}

// =====================================================================
// Kernel 1: char LSTM
// =====================================================================
#define CA_SW   (512 * 68)
#define CA_EMB  (128 * 64)
#define CA_HB   (32 * 64)
#define CA_SB   256
#define CHAR_SMEM_BYTES ((CA_SW + CA_EMB + CA_HB + CA_SB) * 4 + 512 * 4)

__global__ void __launch_bounds__(512, 1)
char_lstm_kernel(const int* __restrict__ ci_g, const int* __restrict__ clen,
                 const float* __restrict__ cemb_g,
                 const float* __restrict__ Wih, const float* __restrict__ Whh,
                 const float* __restrict__ bih, const float* __restrict__ bhh)
{
    extern __shared__ float smA[];
    float* sW    = smA;
    float* cemb  = sW + CA_SW;
    float* hbuf  = cemb + CA_EMB;
    float* sb    = hbuf + CA_HB;
    int*   scidx = (int*)(sb + CA_SB);

    const int tid = threadIdx.x;
    const int wbase = blockIdx.x * 32;

    for (int idx = tid; idx < 512 * 16; idx += 512) {
        int row = idx >> 4, k4 = idx & 15;
        const float* src = (row < 256) ? Wih + (size_t)row * 64 + k4 * 4
                                       : Whh + (size_t)(row - 256) * 64 + k4 * 4;
        *(float4*)&sW[row * 68 + k4 * 4] = *(const float4*)src;
    }
    for (int idx = tid; idx < 128 * 16; idx += 512) {
        int row = idx >> 4, k4 = idx & 15;
        *(float4*)&cemb[row * 64 + k4 * 4] = *(const float4*)(cemb_g + (size_t)row * 64 + k4 * 4);
    }
    if (tid < 256) sb[tid] = bih[tid] + bhh[tid];
    scidx[tid] = ci_g[(size_t)wbase * 16 + tid];
    for (int idx = tid; idx < CA_HB; idx += 512) hbuf[idx] = 0.f;

    const int rt = tid & 63, wt = tid >> 6, w0 = wt * 4;
    int len[4]; float cc[4];
    #pragma unroll
    for (int i = 0; i < 4; i++) { len[i] = clen[wbase + w0 + i]; cc[i] = 0.f; }
    __syncthreads();

    for (int t = 0; t < LC; t++) {
        int ci[4];
        #pragma unroll
        for (int i = 0; i < 4; i++) ci[i] = scidx[(w0 + i) * 16 + t];

        ull acc[4][4];
        #pragma unroll
        for (int i = 0; i < 4; i++)
            #pragma unroll
            for (int q = 0; q < 4; q++) acc[i][q] = 0ull;

        #pragma unroll
        for (int k4 = 0; k4 < 16; k4++) {
            ulonglong2 wv[4];
            #pragma unroll
            for (int q = 0; q < 4; q++)
                wv[q] = *(const ulonglong2*)&sW[(q * 64 + rt) * 68 + k4 * 4];
            #pragma unroll
            for (int i = 0; i < 4; i++) {
                ulonglong2 xv = *(const ulonglong2*)&cemb[ci[i] * 64 + k4 * 4];
                #pragma unroll
                for (int q = 0; q < 4; q++) {
                    acc[i][q] = ffma2(xv.x, wv[q].x, acc[i][q]);
                    acc[i][q] = ffma2(xv.y, wv[q].y, acc[i][q]);
                }
            }
        }
        #pragma unroll
        for (int k4 = 0; k4 < 16; k4++) {
            ulonglong2 wv[4];
            #pragma unroll
            for (int q = 0; q < 4; q++)
                wv[q] = *(const ulonglong2*)&sW[(256 + q * 64 + rt) * 68 + k4 * 4];
            #pragma unroll
            for (int i = 0; i < 4; i++) {
                ulonglong2 hv = *(const ulonglong2*)&hbuf[(w0 + i) * 64 + k4 * 4];
                #pragma unroll
                for (int q = 0; q < 4; q++) {
                    acc[i][q] = ffma2(hv.x, wv[q].x, acc[i][q]);
                    acc[i][q] = ffma2(hv.y, wv[q].y, acc[i][q]);
                }
            }
        }
        __syncthreads();

        float bI = sb[rt], bF = sb[64 + rt], bG = sb[128 + rt], bO = sb[192 + rt];
        #pragma unroll
        for (int i = 0; i < 4; i++) {
            float gi = f2sum(acc[i][0]) + bI;
            float gf = f2sum(acc[i][1]) + bF;
            float gG = f2sum(acc[i][2]) + bG;
            float go = f2sum(acc[i][3]) + bO;
            cc[i] = fmaf(sigm(gf), cc[i], sigm(gi) * tanha(gG));
            float h = sigm(go) * tanha(cc[i]);
            hbuf[(w0 + i) * 64 + rt] = h;
            if (t == len[i] - 1)
                g_char_feat[(size_t)(wbase + w0 + i) * 64 + rt] = h;
        }
        __syncthreads();
    }
}

// =====================================================================
// Kernel 2: gpre
// =====================================================================
#define BP 196
#define GPRE_SMEM_BYTES ((16 + 64) * BP * 4)

__global__ void __launch_bounds__(256, 1)
gpre_kernel(const int* __restrict__ widx, const float* __restrict__ wemb,
            const float* __restrict__ Wih,
            const float* __restrict__ bih, const float* __restrict__ bhh)
{
    extern __shared__ float smB[];
    float* sx = smB;
    float* sw = smB + 16 * BP;

    const int tid = threadIdx.x;
    const int t0 = blockIdx.x * 16;
    const int G0 = blockIdx.y * 64;

    for (int i = tid; i < 16 * 48; i += 256) {
        int tt = i / 48, k4 = i % 48;
        float4 v = (k4 < 32)
            ? *(const float4*)(wemb + (size_t)widx[t0 + tt] * 128 + k4 * 4)
            : *(const float4*)(g_char_feat + (size_t)(t0 + tt) * 64 + (k4 - 32) * 4);
        *(float4*)&sx[tt * BP + k4 * 4] = v;
    }
    for (int i = tid; i < 64 * 48; i += 256) {
        int r = i / 48, k4 = i % 48;
        *(float4*)&sw[r * BP + k4 * 4] = *(const float4*)(Wih + (size_t)(G0 + r) * 192 + k4 * 4);
    }
    __syncthreads();

    const int g = tid & 63, tq = tid >> 6;
    ull ax[4], ay[4];
    #pragma unroll
    for (int i = 0; i < 4; i++) { ax[i] = 0ull; ay[i] = 0ull; }

    #pragma unroll 4
    for (int k4 = 0; k4 < 48; k4++) {
        ulonglong2 wv = *(const ulonglong2*)&sw[g * BP + k4 * 4];
        #pragma unroll
        for (int it = 0; it < 4; it++) {
            ulonglong2 xv = *(const ulonglong2*)&sx[(tq * 4 + it) * BP + k4 * 4];
            ax[it] = ffma2(xv.x, wv.x, ax[it]);
            ay[it] = ffma2(xv.y, wv.y, ay[it]);
        }
    }
    float b = bih[G0 + g] + bhh[G0 + g];
    #pragma unroll
    for (int it = 0; it < 4; it++)
        g_gpre[(size_t)(t0 + tq * 4 + it) * 1024 + G0 + g] = f2sum(ax[it]) + f2sum(ay[it]) + b;
}

// =====================================================================
// Kernel 3: word LSTM. 8-CTA cluster, st.async tx barriers.
// Round-11 structure + wait-shadow optimizations:
//  - m=rank FFMA term hoisted BEFORE the mbar wait, fed from hloc[2][32]
//    (own-CTA h published via STS + __syncthreads each step). Weight
//    slots permuted at load so the main loop has exactly 7 terms
//    (no predicated dead issue slots).
//  - gpre folded into accumulator init on the oct==0 lane (contributes
//    once to the shfl_xor full-sum); post-reduce FADDs deleted.
// hloc W(t-1)->R(t) ordered by the bar; R(t)->W(t+1) ordered by the
// barrier-tx chain (no warp passes wait(t+1) before all warps sent h(t)).
// =====================================================================

#define GFOLD(G_) ((oct == 0) ? (ull)__float_as_uint(G_) : 0ull)

#define WSTEP(BARADDR, PAR, G0_, G1_, G2_, G3_, SH_OFF, ST_DOFF, ST_BOFF, TIDX, DO_EXPECT, DO_STORE, HLR_, HLW_, DO_BAR) \
    do {                                                                                              \
        /* pre-wait: m=rank term from intra-CTA hloc + gp fold (wait shadow) */                       \
        float4 hl_ = *(const float4*)&hloc[HLR_][oct * 4];                                            \
        ull hvA_ = packf2(hl_.x, hl_.y), hvB_ = packf2(hl_.z, hl_.w);                                 \
        ull a0_ = ffma2(hvA_, rwr0.x, GFOLD(G0_)); a0_ = ffma2(hvB_, rwr0.y, a0_);                    \
        ull a1_ = ffma2(hvA_, rwr1.x, GFOLD(G1_)); a1_ = ffma2(hvB_, rwr1.y, a1_);                    \
        ull a2_ = ffma2(hvA_, rwr2.x, GFOLD(G2_)); a2_ = ffma2(hvB_, rwr2.y, a2_);                    \
        ull a3_ = ffma2(hvA_, rwr3.x, GFOLD(G3_)); a3_ = ffma2(hvB_, rwr3.y, a3_);                    \
        mbar_wait_parity((BARADDR), (PAR));                                                           \
        if ((DO_EXPECT) && tid == 0) mbar_expect_tx((BARADDR), 1024);                                 \
        const char* hbb_ = (const char*)sh + (SH_OFF);                                                \
        _Pragma("unroll")                                                                             \
        for (int i_ = 0; i_ < 7; i_++) {                                                              \
            ulonglong2 hv_ = *(const ulonglong2*)(hbb_ + offs[i_]);                                   \
            a0_ = ffma2(hv_.x, rw0[i_].x, a0_); a0_ = ffma2(hv_.y, rw0[i_].y, a0_);                   \
            a1_ = ffma2(hv_.x, rw1[i_].x, a1_); a1_ = ffma2(hv_.y, rw1[i_].y, a1_);                   \
            a2_ = ffma2(hv_.x, rw2[i_].x, a2_); a2_ = ffma2(hv_.y, rw2[i_].y, a2_);                   \
            a3_ = ffma2(hv_.x, rw3[i_].x, a3_); a3_ = ffma2(hv_.y, rw3[i_].y, a3_);                   \
        }                                                                                             \
        float s0_ = f2sum(a0_), s1_ = f2sum(a1_), s2_ = f2sum(a2_), s3_ = f2sum(a3_);                 \
        _Pragma("unroll")                                                                             \
        for (int off_ = 1; off_ <= 4; off_ <<= 1) {                                                   \
            s0_ += __shfl_xor_sync(0xFFFFFFFFu, s0_, off_);                                           \
            s1_ += __shfl_xor_sync(0xFFFFFFFFu, s1_, off_);                                           \
            s2_ += __shfl_xor_sync(0xFFFFFFFFu, s2_, off_);                                           \
            s3_ += __shfl_xor_sync(0xFFFFFFFFu, s3_, off_);                                           \
        }                                                                                             \
        c = fmaf(sigm(s1_), c, sigm(s0_) * tanha(s2_));                                               \
        float h_ = sigm(s3_) * tanha(c);                                                              \
        if (DO_STORE)                                                                                 \
            st_async_b32(dst_my - (ST_DOFF), h_, bar_my - (ST_BOFF));                                 \
        if (is_writer)                                                                                \
            gwp[(size_t)(TIDX) * HW] = h_;                                                            \
        if (DO_BAR) {                                                                                 \
            if (is_writer) hloc[HLW_][jj] = h_;                                                       \
            __syncthreads();                                                                          \
        }                                                                                             \
    } while (0)

__global__ void __launch_bounds__(256, 1) __cluster_dims__(8, 1, 1)
word_lstm_kernel(const float* __restrict__ Whh)
{
    __shared__ float sh[2][256];                        // sh[1] = sh[0] + 1024 B
    __shared__ float hloc[2][32];                       // intra-CTA h exchange
    __shared__ __align__(8) unsigned long long bar2[2]; // bar2[1] = bar2[0] + 8 B

    const int tid = threadIdx.x;
    const int jj  = tid >> 3;     // 0..31 h-unit
    const int oct = tid & 7;      // k octant == this lane's dest CTA
    const uint32_t rank = cluster_rank();
    const int uglob = (int)rank * 32 + jj;

    // permuted weight load: 7 main-loop terms (mm != rank) + hoisted rank term
    ulonglong2 rw0[7], rw1[7], rw2[7], rw3[7];
    ulonglong2 rwr0, rwr1, rwr2, rwr3;
    uint32_t offs[7];
    {
        const float* base = Whh + (size_t)uglob * 256 + oct * 4;
        rwr0 = *(const ulonglong2*)(base + 0 * 65536 + (int)rank * 32);
        rwr1 = *(const ulonglong2*)(base + 1 * 65536 + (int)rank * 32);
        rwr2 = *(const ulonglong2*)(base + 2 * 65536 + (int)rank * 32);
        rwr3 = *(const ulonglong2*)(base + 3 * 65536 + (int)rank * 32);
        int j = 0;
        for (int mm = 0; mm < 8; mm++) {
            if (mm == (int)rank) continue;
            rw0[j] = *(const ulonglong2*)(base + 0 * 65536 + mm * 32);
            rw1[j] = *(const ulonglong2*)(base + 1 * 65536 + mm * 32);
            rw2[j] = *(const ulonglong2*)(base + 2 * 65536 + mm * 32);
            rw3[j] = *(const ulonglong2*)(base + 3 * 65536 + mm * 32);
            offs[j] = (uint32_t)(oct + mm * 8) * 16u;
            j++;
        }
    }

    sh[0][tid] = 0.f;
    sh[1][tid] = 0.f;
    if (tid < 64) hloc[tid >> 5][tid & 31] = 0.f;
    const uint32_t locb0 = smem_u32(&bar2[0]);
    const uint32_t locb1 = smem_u32(&bar2[1]);
    if (tid == 0) {
        mbar_init(locb0, 1);
        mbar_init(locb1, 1);
        mbar_expect_tx(locb0, 1024);
        mbar_expect_tx(locb1, 1024);
    }
    __syncthreads();
    cluster_sync_();

    // per-lane store target: unit uglob's slot / bar1 in dest CTA = oct
    const uint32_t dst_my = mapa_sh(smem_u32(&sh[1][uglob]), (uint32_t)oct);
    const uint32_t bar_my = mapa_sh(locb1, (uint32_t)oct);

    float c = 0.f;
    const bool is_writer = (oct == 0);
    float* const gwp = g_wh + uglob;

    // ---------- t = 0 (no wait; h_prev = 0, c_prev = 0; all lanes) ----------
    {
        const float* gpp0 = g_gpre + uglob;
        float gp0 = gpp0[0], gp2 = gpp0[512], gp3 = gpp0[768];
        c = sigm(gp0) * tanha(gp2);
        float h = sigm(gp3) * tanha(c);
        st_async_b32(dst_my, h, bar_my);
        if (is_writer) { gwp[0] = h; hloc[0][jj] = h; }
        __syncthreads();
    }

    // ---------- interior pairs: m = 0..4093 covers t = 1..8188 ----------
    const float* gpp = g_gpre + 1024 + uglob;   // points at t = 1 row
    float A0, A1, A2, A3;   // gp for odd step t=2m+1
    float B0, B1, B2, B3;   // gp for even step t=2m+2
    A0 = gpp[0];    A1 = gpp[256];  A2 = gpp[512];  A3 = gpp[768];
    B0 = gpp[1024]; B1 = gpp[1280]; B2 = gpp[1536]; B3 = gpp[1792];

    for (int m = 0; m < 4094; m++) {
        // prefetch next pair (t = 2m+3, 2m+4)
        const float* np = gpp + 2048;
        float N0 = np[0],    N1 = np[256],  N2 = np[512],  N3 = np[768];
        float M0 = np[1024], M1 = np[1280], M2 = np[1536], M3 = np[1792];
        const uint32_t ph = (uint32_t)m & 1u;

        // t odd (b=1): wait bar1, read sh[1], store sh[0]/bar0; hloc 0 -> 1
        WSTEP(locb1, ph, A0, A1, A2, A3, 1024u, 1024u, 8u, 2 * m + 1, 1, 1, 0, 1, 1);
        // t even (b=0): wait bar0, read sh[0], store sh[1]/bar1; hloc 1 -> 0
        WSTEP(locb0, ph, B0, B1, B2, B3, 0u, 0u, 0u, 2 * m + 2, 1, 1, 1, 0, 1);

        A0 = N0; A1 = N1; A2 = N2; A3 = N3;
        B0 = M0; B1 = M1; B2 = M2; B3 = M3;
        gpp += 2048;
    }

    // ---------- tail: t = 8189 (odd), 8190 (even), 8191 (odd, no store) ----------
    {
        const float* fp = gpp + 2048;
        float F0 = fp[0], F1 = fp[256], F2 = fp[512], F3 = fp[768];
        WSTEP(locb1, 0u, A0, A1, A2, A3, 1024u, 1024u, 8u, 8189, 1, 1, 0, 1, 1);
        WSTEP(locb0, 0u, B0, B1, B2, B3, 0u, 0u, 0u, 8190, 1, 1, 1, 0, 1);
        WSTEP(locb1, 1u, F0, F1, F2, F3, 1024u, 0u, 0u, 8191, 0, 0, 0, 1, 0);
    }
}

// =====================================================================
// Kernel 4: tag head + log_softmax. 256 blocks x 32 tokens.
// =====================================================================
#define TAG_SW   (256 * 64)
#define TAG_SMEM_BYTES ((TAG_SW + 64) * 4)

__global__ void __launch_bounds__(256, 1)
tag_kernel(const float* __restrict__ tagW, const float* __restrict__ tagb,
           float* __restrict__ out)
{
    extern __shared__ float smT[];
    float* sw = smT;
    float* sb = smT + TAG_SW;

    const int tid = threadIdx.x;
    const int lane = tid & 31, warp = tid >> 5;

    for (int i = tid; i < TAG_SW; i += 256) sw[i] = 0.f;
    if (tid < 64) sb[tid] = (tid < TAGS) ? tagb[tid] : 0.f;
    __syncthreads();
    for (int i = tid; i < TAGS * 256; i += 256) {
        int tg = i >> 8, k = i & 255;
        sw[k * 64 + tg] = tagW[i];
    }
    __syncthreads();

    const bool v1 = (32 + lane) < TAGS;

    #pragma unroll 1
    for (int it = 0; it < 4; it++) {
        const int token = blockIdx.x * 32 + it * 8 + warp;
        const float4* hp4 = (const float4*)(g_wh + (size_t)token * 256);

        float a0 = 0.f, a1 = 0.f;
        #pragma unroll 8
        for (int k4 = 0; k4 < 64; k4++) {
            float4 h = hp4[k4];
            const float* p = sw + k4 * 256 + lane;
            a0 = fmaf(h.x, p[0],   a0);  a1 = fmaf(h.x, p[32],  a1);
            a0 = fmaf(h.y, p[64],  a0);  a1 = fmaf(h.y, p[96],  a1);
            a0 = fmaf(h.z, p[128], a0);  a1 = fmaf(h.z, p[160], a1);
            a0 = fmaf(h.w, p[192], a0);  a1 = fmaf(h.w, p[224], a1);
        }
        a0 += sb[lane];
        a1 += sb[32 + lane];

        float m = fmaxf(a0, v1 ? a1 : -3.4e38f);
        #pragma unroll
        for (int off = 16; off; off >>= 1)
            m = fmaxf(m, __shfl_xor_sync(0xFFFFFFFFu, m, off));
        float e = __expf(a0 - m) + (v1 ? __expf(a1 - m) : 0.f);
        #pragma unroll
        for (int off = 16; off; off >>= 1)
            e += __shfl_xor_sync(0xFFFFFFFFu, e, off);
        float ls = __logf(e);

        out[(size_t)token * TAGS + lane] = a0 - m - ls;
        if (v1) out[(size_t)token * TAGS + 32 + lane] = a1 - m - ls;
    }
}

// =====================================================================
extern "C" void kernel_launch(void* const* d_in, const int* in_sizes, int n_in,
                              void* d_out, int out_size)
{
    const int*   word_idxs = (const int*)d_in[0];
    const int*   char_idxs = (const int*)d_in[1];
    const int*   char_lens = (const int*)d_in[2];
    const float* char_emb  = (const float*)d_in[3];
    const float* char_Wih  = (const float*)d_in[4];
    const float* char_Whh  = (const float*)d_in[5];
    const float* char_bih  = (const float*)d_in[6];
    const float* char_bhh  = (const float*)d_in[7];
    const float* word_emb  = (const float*)d_in[8];
    const float* word_Wih  = (const float*)d_in[9];
    const float* word_Whh  = (const float*)d_in[10];
    const float* word_bih  = (const float*)d_in[11];
    const float* word_bhh  = (const float*)d_in[12];
    const float* tag_W     = (const float*)d_in[13];
    const float* tag_b     = (const float*)d_in[14];
    float* out = (float*)d_out;

    cudaFuncSetAttribute(char_lstm_kernel,
                         cudaFuncAttributeMaxDynamicSharedMemorySize, CHAR_SMEM_BYTES);
    cudaFuncSetAttribute(gpre_kernel,
                         cudaFuncAttributeMaxDynamicSharedMemorySize, GPRE_SMEM_BYTES);
    cudaFuncSetAttribute(tag_kernel,
                         cudaFuncAttributeMaxDynamicSharedMemorySize, TAG_SMEM_BYTES);

    char_lstm_kernel<<<256, 512, CHAR_SMEM_BYTES>>>(
        char_idxs, char_lens, char_emb, char_Wih, char_Whh, char_bih, char_bhh);

    dim3 gb(S / 16, 1024 / 64);
    gpre_kernel<<<gb, 256, GPRE_SMEM_BYTES>>>(
        word_idxs, word_emb, word_Wih, word_bih, word_bhh);

    word_lstm_kernel<<<8, 256>>>(word_Whh);

    tag_kernel<<<S / 32, 256, TAG_SMEM_BYTES>>>(tag_W, tag_b, out);
}

// round 13
// speedup vs baseline: 1.7346x; 1.0167x over previous
#include <cuda_runtime.h>
#include <cstdint>
#include <cstddef>

#define S     8192
#define LC    16
#define CH    64
#define HW    256
#define TAGS  50

typedef unsigned long long ull;

// ---------------- device scratch ----------------
__device__ __align__(256) float g_char_feat[S * CH];        // 2 MB
__device__ __align__(256) float g_gpre[(size_t)S * 4 * HW]; // 32 MB
__device__ __align__(256) float g_wh[(size_t)S * HW];       // 8 MB

// ---------------- helpers ----------------
__device__ __forceinline__ ull ffma2(ull a, ull b, ull c) {
    ull d;
    asm("fma.rn.f32x2 %0, %1, %2, %3;" : "=l"(d) : "l"(a), "l"(b), "l"(c));
    return d;
}
__device__ __forceinline__ ull packf2(float lo, float hi) {
    ull r;
    asm("mov.b64 %0, {%1, %2};" : "=l"(r) : "f"(lo), "f"(hi));
    return r;
}
__device__ __forceinline__ float f2sum(ull a) {
    float lo = __uint_as_float((unsigned)(a & 0xffffffffull));
    float hi = __uint_as_float((unsigned)(a >> 32));
    return lo + hi;
}
__device__ __forceinline__ float tanha(float x) {
    float y; asm("tanh.approx.f32 %0, %1;" : "=f"(y) : "f"(x)); return y;
}
__device__ __forceinline__ float sigm(float x) {       // 1 MUFU
    return fmaf(0.5f, tanha(0.5f * x), 0.5f);
}
__device__ __forceinline__ uint32_t smem_u32(const void* p) {
    return (uint32_t)__cvta_generic_to_shared(p);
}
__device__ __forceinline__ uint32_t cluster_rank() {
    uint32_t r; asm("mov.u32 %0, %%cluster_ctarank;" : "=r"(r)); return r;
}
__device__ __forceinline__ uint32_t mapa_sh(uint32_t addr, uint32_t rank) {
    uint32_t r;
    asm("mapa.shared::cluster.u32 %0, %1, %2;" : "=r"(r) : "r"(addr), "r"(rank));
    return r;
}
__device__ __forceinline__ void mbar_init(uint32_t addr, uint32_t cnt) {
    asm volatile("mbarrier.init.shared.b64 [%0], %1;" :: "r"(addr), "r"(cnt) : "memory");
}
__device__ __forceinline__ void mbar_expect_tx(uint32_t addr, uint32_t bytes) {
    asm volatile("mbarrier.arrive.expect_tx.shared.b64 _, [%0], %1;"
                 :: "r"(addr), "r"(bytes) : "memory");
}
__device__ __forceinline__ void st_async_b32(uint32_t dst, float v, uint32_t mbar) {
    asm volatile("st.async.shared::cluster.mbarrier::complete_tx::bytes.b32 [%0], %1, [%2];"
                 :: "r"(dst), "r"(__float_as_uint(v)), "r"(mbar) : "memory");
}
__device__ __forceinline__ void mbar_wait_parity(uint32_t mbar, uint32_t parity) {
    asm volatile(
        "{\n\t.reg .pred P;\n"
        "W%=:\n\t"
        "mbarrier.try_wait.parity.acquire.cluster.shared::cta.b64 P, [%0], %1, 0x989680;\n\t"
        "@!P bra W%=;\n\t"
        "}" :: "r"(mbar), "r"(parity) : "memory");
}
__device__ __forceinline__ void cluster_sync_() {
    asm volatile("barrier.cluster.arrive.aligned;\n\tbarrier.cluster.wait.aligned;" ::: "memory");
}
__device__ __forceinline__ void named_bar(int id, int cnt) {
    asm volatile("bar.sync %0, %1;" :: "r"(id), "r"(cnt) : "memory");
}

// =====================================================================
// Kernel 1: char LSTM, length-sorted groups + named barriers.
// 256 blocks x 512 threads, 32 words/block. Words rank-sorted by len;
// each 64-thread group processes 4 similar-length words and loops only
// to its own tmax. Group->quartet permutation balances SMSP pairs.
// =====================================================================
#define CA_SW   (512 * 68)
#define CA_EMB  (128 * 64)
#define CA_HB   (32 * 64)
#define CA_SB   256
#define CHAR_SMEM_BYTES ((CA_SW + CA_EMB + CA_HB + CA_SB) * 4 + 512 * 4 + 64 * 4)

__global__ void __launch_bounds__(512, 1)
char_lstm_kernel(const int* __restrict__ ci_g, const int* __restrict__ clen,
                 const float* __restrict__ cemb_g,
                 const float* __restrict__ Wih, const float* __restrict__ Whh,
                 const float* __restrict__ bih, const float* __restrict__ bhh)
{
    extern __shared__ float smA[];
    float* sW    = smA;
    float* cemb  = sW + CA_SW;
    float* hbuf  = cemb + CA_EMB;
    float* sb    = hbuf + CA_HB;
    int*   scidx = (int*)(sb + CA_SB);       // [32][16]
    int*   slens = scidx + 512;              // [32]
    int*   ssort = slens + 32;               // [32]

    const int tid = threadIdx.x;
    const int wbase = blockIdx.x * 32;

    for (int idx = tid; idx < 512 * 16; idx += 512) {
        int row = idx >> 4, k4 = idx & 15;
        const float* src = (row < 256) ? Wih + (size_t)row * 64 + k4 * 4
                                       : Whh + (size_t)(row - 256) * 64 + k4 * 4;
        *(float4*)&sW[row * 68 + k4 * 4] = *(const float4*)src;
    }
    for (int idx = tid; idx < 128 * 16; idx += 512) {
        int row = idx >> 4, k4 = idx & 15;
        *(float4*)&cemb[row * 64 + k4 * 4] = *(const float4*)(cemb_g + (size_t)row * 64 + k4 * 4);
    }
    if (tid < 256) sb[tid] = bih[tid] + bhh[tid];
    scidx[tid] = ci_g[(size_t)wbase * 16 + tid];
    if (tid < 32) slens[tid] = clen[wbase + tid];
    for (int idx = tid; idx < CA_HB; idx += 512) hbuf[idx] = 0.f;
    __syncthreads();

    // rank-sort the 32 words by (len, idx) ascending
    if (tid < 32) {
        int ml = slens[tid];
        int rank = 0;
        #pragma unroll
        for (int j = 0; j < 32; j++) {
            int lj = slens[j];
            rank += (lj < ml || (lj == ml && j < tid)) ? 1 : 0;
        }
        ssort[rank] = tid;
    }
    __syncthreads();

    const int rt = tid & 63, wt = tid >> 6, w0 = wt * 4;
    // even groups (SMSP 0/1) take quartets {0,3,4,7}; odd (SMSP 2/3) {1,2,5,6}
    const int perm_tab[8] = {0, 1, 3, 2, 4, 5, 7, 6};
    const int q0 = perm_tab[wt] * 4;

    int wloc[4], len[4]; float cc[4];
    #pragma unroll
    for (int i = 0; i < 4; i++) {
        wloc[i] = ssort[q0 + i];
        len[i]  = slens[wloc[i]];
        cc[i]   = 0.f;
    }
    const int tmax = len[3];   // ascending within quartet
    const int barid = wt + 1;

    for (int t = 0; t < tmax; t++) {
        int ci[4];
        #pragma unroll
        for (int i = 0; i < 4; i++) ci[i] = scidx[wloc[i] * 16 + t];

        ull acc[4][4];
        #pragma unroll
        for (int i = 0; i < 4; i++)
            #pragma unroll
            for (int q = 0; q < 4; q++) acc[i][q] = 0ull;

        #pragma unroll
        for (int k4 = 0; k4 < 16; k4++) {
            ulonglong2 wv[4];
            #pragma unroll
            for (int q = 0; q < 4; q++)
                wv[q] = *(const ulonglong2*)&sW[(q * 64 + rt) * 68 + k4 * 4];
            #pragma unroll
            for (int i = 0; i < 4; i++) {
                ulonglong2 xv = *(const ulonglong2*)&cemb[ci[i] * 64 + k4 * 4];
                #pragma unroll
                for (int q = 0; q < 4; q++) {
                    acc[i][q] = ffma2(xv.x, wv[q].x, acc[i][q]);
                    acc[i][q] = ffma2(xv.y, wv[q].y, acc[i][q]);
                }
            }
        }
        #pragma unroll
        for (int k4 = 0; k4 < 16; k4++) {
            ulonglong2 wv[4];
            #pragma unroll
            for (int q = 0; q < 4; q++)
                wv[q] = *(const ulonglong2*)&sW[(256 + q * 64 + rt) * 68 + k4 * 4];
            #pragma unroll
            for (int i = 0; i < 4; i++) {
                ulonglong2 hv = *(const ulonglong2*)&hbuf[(w0 + i) * 64 + k4 * 4];
                #pragma unroll
                for (int q = 0; q < 4; q++) {
                    acc[i][q] = ffma2(hv.x, wv[q].x, acc[i][q]);
                    acc[i][q] = ffma2(hv.y, wv[q].y, acc[i][q]);
                }
            }
        }
        named_bar(barid, 64);   // group-private hbuf: reads done before rewrite

        float bI = sb[rt], bF = sb[64 + rt], bG = sb[128 + rt], bO = sb[192 + rt];
        #pragma unroll
        for (int i = 0; i < 4; i++) {
            float gi = f2sum(acc[i][0]) + bI;
            float gf = f2sum(acc[i][1]) + bF;
            float gG = f2sum(acc[i][2]) + bG;
            float go = f2sum(acc[i][3]) + bO;
            cc[i] = fmaf(sigm(gf), cc[i], sigm(gi) * tanha(gG));
            float h = sigm(go) * tanha(cc[i]);
            hbuf[(w0 + i) * 64 + rt] = h;
            if (t == len[i] - 1)
                g_char_feat[(size_t)(wbase + wloc[i]) * 64 + rt] = h;
        }
        named_bar(barid, 64);
    }
}

// =====================================================================
// Kernel 2: gpre (unchanged)
// =====================================================================
#define BP 196
#define GPRE_SMEM_BYTES ((16 + 64) * BP * 4)

__global__ void __launch_bounds__(256, 1)
gpre_kernel(const int* __restrict__ widx, const float* __restrict__ wemb,
            const float* __restrict__ Wih,
            const float* __restrict__ bih, const float* __restrict__ bhh)
{
    extern __shared__ float smB[];
    float* sx = smB;
    float* sw = smB + 16 * BP;

    const int tid = threadIdx.x;
    const int t0 = blockIdx.x * 16;
    const int G0 = blockIdx.y * 64;

    for (int i = tid; i < 16 * 48; i += 256) {
        int tt = i / 48, k4 = i % 48;
        float4 v = (k4 < 32)
            ? *(const float4*)(wemb + (size_t)widx[t0 + tt] * 128 + k4 * 4)
            : *(const float4*)(g_char_feat + (size_t)(t0 + tt) * 64 + (k4 - 32) * 4);
        *(float4*)&sx[tt * BP + k4 * 4] = v;
    }
    for (int i = tid; i < 64 * 48; i += 256) {
        int r = i / 48, k4 = i % 48;
        *(float4*)&sw[r * BP + k4 * 4] = *(const float4*)(Wih + (size_t)(G0 + r) * 192 + k4 * 4);
    }
    __syncthreads();

    const int g = tid & 63, tq = tid >> 6;
    ull ax[4], ay[4];
    #pragma unroll
    for (int i = 0; i < 4; i++) { ax[i] = 0ull; ay[i] = 0ull; }

    #pragma unroll 4
    for (int k4 = 0; k4 < 48; k4++) {
        ulonglong2 wv = *(const ulonglong2*)&sw[g * BP + k4 * 4];
        #pragma unroll
        for (int it = 0; it < 4; it++) {
            ulonglong2 xv = *(const ulonglong2*)&sx[(tq * 4 + it) * BP + k4 * 4];
            ax[it] = ffma2(xv.x, wv.x, ax[it]);
            ay[it] = ffma2(xv.y, wv.y, ay[it]);
        }
    }
    float b = bih[G0 + g] + bhh[G0 + g];
    #pragma unroll
    for (int it = 0; it < 4; it++)
        g_gpre[(size_t)(t0 + tq * 4 + it) * 1024 + G0 + g] = f2sum(ax[it]) + f2sum(ay[it]) + b;
}

// =====================================================================
// Kernel 3: word LSTM (unchanged from round 12)
// =====================================================================

#define GFOLD(G_) ((oct == 0) ? (ull)__float_as_uint(G_) : 0ull)

#define WSTEP(BARADDR, PAR, G0_, G1_, G2_, G3_, SH_OFF, ST_DOFF, ST_BOFF, TIDX, DO_EXPECT, DO_STORE, HLR_, HLW_, DO_BAR) \
    do {                                                                                              \
        float4 hl_ = *(const float4*)&hloc[HLR_][oct * 4];                                            \
        ull hvA_ = packf2(hl_.x, hl_.y), hvB_ = packf2(hl_.z, hl_.w);                                 \
        ull a0_ = ffma2(hvA_, rwr0.x, GFOLD(G0_)); a0_ = ffma2(hvB_, rwr0.y, a0_);                    \
        ull a1_ = ffma2(hvA_, rwr1.x, GFOLD(G1_)); a1_ = ffma2(hvB_, rwr1.y, a1_);                    \
        ull a2_ = ffma2(hvA_, rwr2.x, GFOLD(G2_)); a2_ = ffma2(hvB_, rwr2.y, a2_);                    \
        ull a3_ = ffma2(hvA_, rwr3.x, GFOLD(G3_)); a3_ = ffma2(hvB_, rwr3.y, a3_);                    \
        mbar_wait_parity((BARADDR), (PAR));                                                           \
        if ((DO_EXPECT) && tid == 0) mbar_expect_tx((BARADDR), 1024);                                 \
        const char* hbb_ = (const char*)sh + (SH_OFF);                                                \
        _Pragma("unroll")                                                                             \
        for (int i_ = 0; i_ < 7; i_++) {                                                              \
            ulonglong2 hv_ = *(const ulonglong2*)(hbb_ + offs[i_]);                                   \
            a0_ = ffma2(hv_.x, rw0[i_].x, a0_); a0_ = ffma2(hv_.y, rw0[i_].y, a0_);                   \
            a1_ = ffma2(hv_.x, rw1[i_].x, a1_); a1_ = ffma2(hv_.y, rw1[i_].y, a1_);                   \
            a2_ = ffma2(hv_.x, rw2[i_].x, a2_); a2_ = ffma2(hv_.y, rw2[i_].y, a2_);                   \
            a3_ = ffma2(hv_.x, rw3[i_].x, a3_); a3_ = ffma2(hv_.y, rw3[i_].y, a3_);                   \
        }                                                                                             \
        float s0_ = f2sum(a0_), s1_ = f2sum(a1_), s2_ = f2sum(a2_), s3_ = f2sum(a3_);                 \
        _Pragma("unroll")                                                                             \
        for (int off_ = 1; off_ <= 4; off_ <<= 1) {                                                   \
            s0_ += __shfl_xor_sync(0xFFFFFFFFu, s0_, off_);                                           \
            s1_ += __shfl_xor_sync(0xFFFFFFFFu, s1_, off_);                                           \
            s2_ += __shfl_xor_sync(0xFFFFFFFFu, s2_, off_);                                           \
            s3_ += __shfl_xor_sync(0xFFFFFFFFu, s3_, off_);                                           \
        }                                                                                             \
        c = fmaf(sigm(s1_), c, sigm(s0_) * tanha(s2_));                                               \
        float h_ = sigm(s3_) * tanha(c);                                                              \
        if (DO_STORE)                                                                                 \
            st_async_b32(dst_my - (ST_DOFF), h_, bar_my - (ST_BOFF));                                 \
        if (is_writer)                                                                                \
            gwp[(size_t)(TIDX) * HW] = h_;                                                            \
        if (DO_BAR) {                                                                                 \
            if (is_writer) hloc[HLW_][jj] = h_;                                                       \
            __syncthreads();                                                                          \
        }                                                                                             \
    } while (0)

__global__ void __launch_bounds__(256, 1) __cluster_dims__(8, 1, 1)
word_lstm_kernel(const float* __restrict__ Whh)
{
    __shared__ float sh[2][256];                        // sh[1] = sh[0] + 1024 B
    __shared__ float hloc[2][32];                       // intra-CTA h exchange
    __shared__ __align__(8) unsigned long long bar2[2]; // bar2[1] = bar2[0] + 8 B

    const int tid = threadIdx.x;
    const int jj  = tid >> 3;
    const int oct = tid & 7;
    const uint32_t rank = cluster_rank();
    const int uglob = (int)rank * 32 + jj;

    ulonglong2 rw0[7], rw1[7], rw2[7], rw3[7];
    ulonglong2 rwr0, rwr1, rwr2, rwr3;
    uint32_t offs[7];
    {
        const float* base = Whh + (size_t)uglob * 256 + oct * 4;
        rwr0 = *(const ulonglong2*)(base + 0 * 65536 + (int)rank * 32);
        rwr1 = *(const ulonglong2*)(base + 1 * 65536 + (int)rank * 32);
        rwr2 = *(const ulonglong2*)(base + 2 * 65536 + (int)rank * 32);
        rwr3 = *(const ulonglong2*)(base + 3 * 65536 + (int)rank * 32);
        int j = 0;
        for (int mm = 0; mm < 8; mm++) {
            if (mm == (int)rank) continue;
            rw0[j] = *(const ulonglong2*)(base + 0 * 65536 + mm * 32);
            rw1[j] = *(const ulonglong2*)(base + 1 * 65536 + mm * 32);
            rw2[j] = *(const ulonglong2*)(base + 2 * 65536 + mm * 32);
            rw3[j] = *(const ulonglong2*)(base + 3 * 65536 + mm * 32);
            offs[j] = (uint32_t)(oct + mm * 8) * 16u;
            j++;
        }
    }

    sh[0][tid] = 0.f;
    sh[1][tid] = 0.f;
    if (tid < 64) hloc[tid >> 5][tid & 31] = 0.f;
    const uint32_t locb0 = smem_u32(&bar2[0]);
    const uint32_t locb1 = smem_u32(&bar2[1]);
    if (tid == 0) {
        mbar_init(locb0, 1);
        mbar_init(locb1, 1);
        mbar_expect_tx(locb0, 1024);
        mbar_expect_tx(locb1, 1024);
    }
    __syncthreads();
    cluster_sync_();

    const uint32_t dst_my = mapa_sh(smem_u32(&sh[1][uglob]), (uint32_t)oct);
    const uint32_t bar_my = mapa_sh(locb1, (uint32_t)oct);

    float c = 0.f;
    const bool is_writer = (oct == 0);
    float* const gwp = g_wh + uglob;

    // ---------- t = 0 ----------
    {
        const float* gpp0 = g_gpre + uglob;
        float gp0 = gpp0[0], gp2 = gpp0[512], gp3 = gpp0[768];
        c = sigm(gp0) * tanha(gp2);
        float h = sigm(gp3) * tanha(c);
        st_async_b32(dst_my, h, bar_my);
        if (is_writer) { gwp[0] = h; hloc[0][jj] = h; }
        __syncthreads();
    }

    // ---------- interior pairs: m = 0..4093 covers t = 1..8188 ----------
    const float* gpp = g_gpre + 1024 + uglob;
    float A0, A1, A2, A3;
    float B0, B1, B2, B3;
    A0 = gpp[0];    A1 = gpp[256];  A2 = gpp[512];  A3 = gpp[768];
    B0 = gpp[1024]; B1 = gpp[1280]; B2 = gpp[1536]; B3 = gpp[1792];

    for (int m = 0; m < 4094; m++) {
        const float* np = gpp + 2048;
        float N0 = np[0],    N1 = np[256],  N2 = np[512],  N3 = np[768];
        float M0 = np[1024], M1 = np[1280], M2 = np[1536], M3 = np[1792];
        const uint32_t ph = (uint32_t)m & 1u;

        WSTEP(locb1, ph, A0, A1, A2, A3, 1024u, 1024u, 8u, 2 * m + 1, 1, 1, 0, 1, 1);
        WSTEP(locb0, ph, B0, B1, B2, B3, 0u, 0u, 0u, 2 * m + 2, 1, 1, 1, 0, 1);

        A0 = N0; A1 = N1; A2 = N2; A3 = N3;
        B0 = M0; B1 = M1; B2 = M2; B3 = M3;
        gpp += 2048;
    }

    // ---------- tail: t = 8189, 8190, 8191 ----------
    {
        const float* fp = gpp + 2048;
        float F0 = fp[0], F1 = fp[256], F2 = fp[512], F3 = fp[768];
        WSTEP(locb1, 0u, A0, A1, A2, A3, 1024u, 1024u, 8u, 8189, 1, 1, 0, 1, 1);
        WSTEP(locb0, 0u, B0, B1, B2, B3, 0u, 0u, 0u, 8190, 1, 1, 1, 0, 1);
        WSTEP(locb1, 1u, F0, F1, F2, F3, 1024u, 0u, 0u, 8191, 0, 0, 0, 1, 0);
    }
}

// =====================================================================
// Kernel 4: tag head + log_softmax (unchanged)
// =====================================================================
#define TAG_SW   (256 * 64)
#define TAG_SMEM_BYTES ((TAG_SW + 64) * 4)

__global__ void __launch_bounds__(256, 1)
tag_kernel(const float* __restrict__ tagW, const float* __restrict__ tagb,
           float* __restrict__ out)
{
    extern __shared__ float smT[];
    float* sw = smT;
    float* sb = smT + TAG_SW;

    const int tid = threadIdx.x;
    const int lane = tid & 31, warp = tid >> 5;

    for (int i = tid; i < TAG_SW; i += 256) sw[i] = 0.f;
    if (tid < 64) sb[tid] = (tid < TAGS) ? tagb[tid] : 0.f;
    __syncthreads();
    for (int i = tid; i < TAGS * 256; i += 256) {
        int tg = i >> 8, k = i & 255;
        sw[k * 64 + tg] = tagW[i];
    }
    __syncthreads();

    const bool v1 = (32 + lane) < TAGS;

    #pragma unroll 1
    for (int it = 0; it < 4; it++) {
        const int token = blockIdx.x * 32 + it * 8 + warp;
        const float4* hp4 = (const float4*)(g_wh + (size_t)token * 256);

        float a0 = 0.f, a1 = 0.f;
        #pragma unroll 8
        for (int k4 = 0; k4 < 64; k4++) {
            float4 h = hp4[k4];
            const float* p = sw + k4 * 256 + lane;
            a0 = fmaf(h.x, p[0],   a0);  a1 = fmaf(h.x, p[32],  a1);
            a0 = fmaf(h.y, p[64],  a0);  a1 = fmaf(h.y, p[96],  a1);
            a0 = fmaf(h.z, p[128], a0);  a1 = fmaf(h.z, p[160], a1);
            a0 = fmaf(h.w, p[192], a0);  a1 = fmaf(h.w, p[224], a1);
        }
        a0 += sb[lane];
        a1 += sb[32 + lane];

        float m = fmaxf(a0, v1 ? a1 : -3.4e38f);
        #pragma unroll
        for (int off = 16; off; off >>= 1)
            m = fmaxf(m, __shfl_xor_sync(0xFFFFFFFFu, m, off));
        float e = __expf(a0 - m) + (v1 ? __expf(a1 - m) : 0.f);
        #pragma unroll
        for (int off = 16; off; off >>= 1)
            e += __shfl_xor_sync(0xFFFFFFFFu, e, off);
        float ls = __logf(e);

        out[(size_t)token * TAGS + lane] = a0 - m - ls;
        if (v1) out[(size_t)token * TAGS + 32 + lane] = a1 - m - ls;
    }
}

// =====================================================================
extern "C" void kernel_launch(void* const* d_in, const int* in_sizes, int n_in,
                              void* d_out, int out_size)
{
    const int*   word_idxs = (const int*)d_in[0];
    const int*   char_idxs = (const int*)d_in[1];
    const int*   char_lens = (const int*)d_in[2];
    const float* char_emb  = (const float*)d_in[3];
    const float* char_Wih  = (const float*)d_in[4];
    const float* char_Whh  = (const float*)d_in[5];
    const float* char_bih  = (const float*)d_in[6];
    const float* char_bhh  = (const float*)d_in[7];
    const float* word_emb  = (const float*)d_in[8];
    const float* word_Wih  = (const float*)d_in[9];
    const float* word_Whh  = (const float*)d_in[10];
    const float* word_bih  = (const float*)d_in[11];
    const float* word_bhh  = (const float*)d_in[12];
    const float* tag_W     = (const float*)d_in[13];
    const float* tag_b     = (const float*)d_in[14];
    float* out = (float*)d_out;

    cudaFuncSetAttribute(char_lstm_kernel,
                         cudaFuncAttributeMaxDynamicSharedMemorySize, CHAR_SMEM_BYTES);
    cudaFuncSetAttribute(gpre_kernel,
                         cudaFuncAttributeMaxDynamicSharedMemorySize, GPRE_SMEM_BYTES);
    cudaFuncSetAttribute(tag_kernel,
                         cudaFuncAttributeMaxDynamicSharedMemorySize, TAG_SMEM_BYTES);

    char_lstm_kernel<<<256, 512, CHAR_SMEM_BYTES>>>(
        char_idxs, char_lens, char_emb, char_Wih, char_Whh, char_bih, char_bhh);

    dim3 gb(S / 16, 1024 / 64);
    gpre_kernel<<<gb, 256, GPRE_SMEM_BYTES>>>(
        word_idxs, word_emb, word_Wih, word_bih, word_bhh);

    word_lstm_kernel<<<8, 256>>>(word_Whh);

    tag_kernel<<<S / 32, 256, TAG_SMEM_BYTES>>>(tag_W, tag_b, out);
}